// round 11
// baseline (speedup 1.0000x reference)
#include <cuda_runtime.h>
#include <cuda_bf16.h>
#include <math.h>
#include <stdint.h>

#define B_  2
#define H_  8
#define T_  2048
#define KD  128
#define BH  (B_*H_)
#define BN  64
#define NKT (T_/BN)      // 32 kv tiles of 64
#define NQT (T_/128)     // 16 q tiles of 128
#define NTASK (BH*NQT)   // 256
#define NELEM (BH*T_*KD)
#define GRID_MAIN 148

// ---------------- device-global scratch -----------------------------------
__device__ float d_g [BH*T_];
__device__ float d_cm[BH*T_];
__device__ float d_nf[BH*T_];
__device__ float d_ce[BH*T_];
__device__ float d_Gt[BH*NKT];
__device__ unsigned int d_task_ctr;

__device__ __nv_bfloat16 d_kh[NELEM], d_kl[NELEM];
__device__ __nv_bfloat16 d_vh[NELEM], d_vl[NELEM];

// ---------------- helpers -------------------------------------------------
__device__ __forceinline__ uint32_t smem_u32(const void* p) {
    uint32_t a;
    asm("{ .reg .u64 t; cvta.to.shared.u64 t, %1; cvt.u32.u64 %0, t; }"
        : "=r"(a) : "l"(p));
    return a;
}

#define CP16(dst, src) \
    asm volatile("cp.async.cg.shared.global [%0], [%1], 16;" :: "r"(dst), "l"(src))
#define CP_COMMIT() asm volatile("cp.async.commit_group;" ::: "memory")
#define CP_WAIT0()  asm volatile("cp.async.wait_group 0;" ::: "memory")

__device__ __forceinline__ void ldm_x4(uint32_t* r, uint32_t addr) {
    asm volatile("ldmatrix.sync.aligned.m8n8.x4.shared.b16 {%0,%1,%2,%3}, [%4];"
        : "=r"(r[0]), "=r"(r[1]), "=r"(r[2]), "=r"(r[3]) : "r"(addr));
}
__device__ __forceinline__ void ldm_x4_t(uint32_t* r, uint32_t addr) {
    asm volatile("ldmatrix.sync.aligned.m8n8.x4.trans.shared.b16 {%0,%1,%2,%3}, [%4];"
        : "=r"(r[0]), "=r"(r[1]), "=r"(r[2]), "=r"(r[3]) : "r"(addr));
}
__device__ __forceinline__ void mma16816(float (&d)[4], const uint32_t (&a)[4],
                                         uint32_t b0, uint32_t b1) {
    asm volatile(
        "mma.sync.aligned.m16n8k16.row.col.f32.bf16.bf16.f32 "
        "{%0,%1,%2,%3}, {%4,%5,%6,%7}, {%8,%9}, {%0,%1,%2,%3};"
        : "+f"(d[0]), "+f"(d[1]), "+f"(d[2]), "+f"(d[3])
        : "r"(a[0]), "r"(a[1]), "r"(a[2]), "r"(a[3]), "r"(b0), "r"(b1));
}

// fast split: hi = truncate-to-bf16, lo = RN(x - hi)
__device__ __forceinline__ void split2f(float a, float b, uint32_t& h, uint32_t& l) {
    uint32_t ua = __float_as_uint(a) & 0xffff0000u;
    uint32_t ub = __float_as_uint(b) & 0xffff0000u;
    float la = a - __uint_as_float(ua);
    float lb = b - __uint_as_float(ub);
    h = (ua >> 16) | ub;
    __nv_bfloat162 p = __float22bfloat162_rn(make_float2(la, lb));
    l = *reinterpret_cast<uint32_t*>(&p);
}

// swizzled chunk offset: 16 chunks (16B) per 256B row
__device__ __forceinline__ uint32_t swzo(int row, int ck) {
    return (uint32_t)((row * 16 + (ck ^ (row & 7))) << 4);
}

// ---------------- smem layout (bytes) -------------------------------------
#define OFF_QH   0
#define OFF_QL   32768
#define OFF_TILE(b) (65536 + (b) * 65536)
#define P_KH 0
#define P_KL 16384
#define P_VH 32768
#define P_VL 49152
#define OFF_CE(b) (196608 + (b) * 256)
#define OFF_G(b)  (197120 + (b) * 256)
#define SMEM_TOTAL 197632

// ---------------------------------------------------------------------------
// Fused pre-pass. Blocks [0,16): per-head gate scan (FIRST, overlaps splat).
// Blocks [16,4112): split K/V into bf16 hi/lo planes.
// ---------------------------------------------------------------------------
__global__ void fused_pre(const float* __restrict__ k, const float* __restrict__ v,
                          const float* __restrict__ ig, const float* __restrict__ fg) {
    __shared__ double sh[256];
    __shared__ float shf[256];
    __shared__ float tm[32];
    const int tid = threadIdx.x;

    if (blockIdx.x >= 16) {
        int i = (blockIdx.x - 16) * 256 + tid;
        float4 kv = ((const float4*)k)[i];
        float4 vv = ((const float4*)v)[i];
        uint32_t h0, l0, h1, l1;
        split2f(kv.x, kv.y, h0, l0); split2f(kv.z, kv.w, h1, l1);
        ((uint2*)d_kh)[i] = make_uint2(h0, h1);
        ((uint2*)d_kl)[i] = make_uint2(l0, l1);
        split2f(vv.x, vv.y, h0, l0); split2f(vv.z, vv.w, h1, l1);
        ((uint2*)d_vh)[i] = make_uint2(h0, h1);
        ((uint2*)d_vl)[i] = make_uint2(l0, l1);
        return;
    }

    const int bh = blockIdx.x;
    if (bh == 0 && tid == 0) d_task_ctr = GRID_MAIN;
    const float* fp = fg + (size_t)bh * T_;
    const float* ip = ig + (size_t)bh * T_;
    const int base = tid * 8;

    double lf[8]; float gi[8];
#pragma unroll
    for (int r = 0; r < 8; r++) {
        float x = fp[base + r];
        lf[r] = (double)(fminf(x, 0.f) - log1pf(__expf(-fabsf(x))));
        gi[r] = ip[base + r];
    }
    double run = 0.0, fc[8];
#pragma unroll
    for (int r = 0; r < 8; r++) { run += lf[r]; fc[r] = run; }

    sh[tid] = run; __syncthreads();
    for (int off = 1; off < 256; off <<= 1) {
        double t = 0.0; if (tid >= off) t = sh[tid - off];
        __syncthreads();
        if (tid >= off) sh[tid] += t;
        __syncthreads();
    }
    double addoff = sh[tid] - run;

    double g[8], gm[8], runm = -1e300;
#pragma unroll
    for (int r = 0; r < 8; r++) {
        fc[r] += addoff;
        g[r]  = (double)gi[r] - fc[r];
        runm  = fmax(runm, g[r]);
        gm[r] = runm;
    }
    __syncthreads();
    sh[tid] = runm; __syncthreads();
    for (int off = 1; off < 256; off <<= 1) {
        double t = -1e300; if (tid >= off) t = sh[tid - off];
        __syncthreads();
        if (tid >= off) sh[tid] = fmax(sh[tid], t);
        __syncthreads();
    }
    double prevmax = (tid == 0) ? -1e300 : sh[tid - 1];

    float gf[8];
#pragma unroll
    for (int r = 0; r < 8; r++) {
        double cm = fmax(prevmax, gm[r]);
        gf[r] = (float)g[r];
        d_g [bh*T_ + base + r] = gf[r];
        d_cm[bh*T_ + base + r] = (float)cm;
        d_nf[bh*T_ + base + r] = __expf((float)(-(fc[r] + cm)));
    }

    float lmax = gf[0];
#pragma unroll
    for (int r = 1; r < 8; r++) lmax = fmaxf(lmax, gf[r]);
    __syncthreads();
    shf[tid] = lmax; __syncthreads();
    if (tid < 32) {
        float mx = shf[tid * 8];
#pragma unroll
        for (int u = 1; u < 8; u++) mx = fmaxf(mx, shf[tid * 8 + u]);
        tm[tid] = mx;
        d_Gt[bh*NKT + tid] = mx;
    }
    __syncthreads();
    float G = tm[tid >> 3];
#pragma unroll
    for (int r = 0; r < 8; r++)
        d_ce[bh*T_ + base + r] = __expf(gf[r] - G);
}

// ---------------------------------------------------------------------------
// tile loader: 64-row K/V bf16 planes + aux vectors, cp.async, 256 threads
// ---------------------------------------------------------------------------
__device__ __forceinline__ void load_tile(uint32_t sb, int b, int bh, int kt, int tid) {
    size_t gbase = ((size_t)(bh * T_ + kt * BN)) * KD;
    const char* gkh = (const char*)d_kh + gbase * 2;
    const char* gkl = (const char*)d_kl + gbase * 2;
    const char* gvh = (const char*)d_vh + gbase * 2;
    const char* gvl = (const char*)d_vl + gbase * 2;
    uint32_t tb = sb + OFF_TILE(b);
#pragma unroll
    for (int u = 0; u < 4; u++) {
        int ch = tid + u * 256;
        int r = ch >> 4, c = ch & 15;
        uint32_t a = swzo(r, c);
        size_t go = (size_t)ch * 16;
        CP16(tb + P_KH + a, gkh + go);
        CP16(tb + P_KL + a, gkl + go);
        CP16(tb + P_VH + a, gvh + go);
        CP16(tb + P_VL + a, gvl + go);
    }
    if (tid < 16) {
        CP16(sb + OFF_CE(b) + tid * 16,
             (const char*)(d_ce + bh * T_ + kt * BN) + tid * 16);
    } else if (tid < 32) {
        CP16(sb + OFF_G(b) + (tid - 16) * 16,
             (const char*)(d_g + bh * T_ + kt * BN) + (tid - 16) * 16);
    }
}

// ---------------------------------------------------------------------------
// Main kernel: 256 threads (8 warps), BM=128, BN=64, persistent queue.
// Each iteration split into two independent N-halves; warps 0-3 process
// halves in order {0,1}, warps 4-7 in order {1,0} -> every SMSP always has
// one warp in an MMA phase while the other is in an epilogue phase.
// ---------------------------------------------------------------------------
__global__ void __launch_bounds__(256, 1)
mlstm_mma(const float* __restrict__ q, float* __restrict__ out) {
    extern __shared__ char smem[];
    __shared__ int sh_task;
    const uint32_t sb = smem_u32(smem);
    const int tid  = threadIdx.x;
    const int lane = tid & 31;
    const int wid  = tid >> 5;
    const int m0   = wid * 16;
    const int horder = (wid >> 2) & 1;        // warp-group half order
    const float scale = 0.08838834764831845f; // 128^-0.5

    int task = blockIdx.x;
    for (;;) {
        if (task >= NTASK) return;
        const int bh = task & 15;
        const int qt = (NQT - 1) - (task >> 4);    // descending work
        const int NT = 2 * qt + 2;
        const int q0 = qt * 128;

        // kick tile 0 fetch first, then stage Q planes (disjoint smem)
        load_tile(sb, 0, bh, 0, tid);
        CP_COMMIT();

        const float* qbase = q + (size_t)(bh * T_ + q0) * KD;
#pragma unroll
        for (int u = 0; u < 8; u++) {
            int ch = tid + u * 256;
            int r = ch >> 4, c = ch & 15;
            const float4* src = (const float4*)(qbase + r * 128 + c * 8);
            float4 x0 = src[0], x1 = src[1];
            uint32_t h0, l0, h1, l1, h2, l2, h3, l3;
            split2f(x0.x * scale, x0.y * scale, h0, l0);
            split2f(x0.z * scale, x0.w * scale, h1, l1);
            split2f(x1.x * scale, x1.y * scale, h2, l2);
            split2f(x1.z * scale, x1.w * scale, h3, l3);
            uint32_t a = swzo(r, c);
            *(uint4*)(smem + OFF_QH + a) = make_uint4(h0, h1, h2, h3);
            *(uint4*)(smem + OFF_QL + a) = make_uint4(l0, l1, l2, l3);
        }

        const int rowg0 = q0 + m0 + (lane >> 2);
        const int rowg1 = rowg0 + 8;
        const float cm0 = d_cm[bh * T_ + rowg0];
        const float cm1 = d_cm[bh * T_ + rowg1];
        const float nf0 = d_nf[bh * T_ + rowg0];
        const float nf1 = d_nf[bh * T_ + rowg1];

        float hacc[16][4];
#pragma unroll
        for (int i = 0; i < 16; i++)
#pragma unroll
            for (int j = 0; j < 4; j++) hacc[i][j] = 0.f;
        float rs0 = 0.f, rs1 = 0.f;

        CP_WAIT0();
        __syncthreads();

        for (int kt = 0; kt < NT; kt++) {
            const int b = kt & 1;
            if (kt + 1 < NT) { load_tile(sb, 1 - b, bh, kt + 1, tid); CP_COMMIT(); }
            const uint32_t tb = sb + OFF_TILE(b);
            const float Gtv = __ldg(&d_Gt[bh * NKT + kt]);
            const float* ce = (const float*)(smem + OFF_CE(b));
            const float* gg = (const float*)(smem + OFF_G(b));
            const float rr0 = __expf(Gtv - cm0);
            const float rr1 = __expf(Gtv - cm1);
            const int wmrow = q0 + m0;

#pragma unroll
            for (int hh = 0; hh < 2; hh++) {
                const int h = hh ^ horder;             // this warp's half order
                const int smin_h = kt * BN + 32 * h;   // first s-col of half
                const bool fullmask = (smin_h > wmrow + 15);
                if (fullmask) continue;
                const bool partial = (smin_h + 31 > wmrow);

                // ===== MMA1(half): S cols [32h,32h+32) =====
                float sa[4][4];
#pragma unroll
                for (int i = 0; i < 4; i++)
#pragma unroll
                    for (int j = 0; j < 4; j++) sa[i][j] = 0.f;

#pragma unroll
                for (int kb = 0; kb < 8; kb++) {
                    uint32_t qhf[4], qlf[4];
                    {
                        int row = m0 + (lane & 15);
                        int ck  = 2 * kb + (lane >> 4);
                        ldm_x4(qhf, sb + OFF_QH + swzo(row, ck));
                        ldm_x4(qlf, sb + OFF_QL + swzo(row, ck));
                    }
                    uint32_t bhf[2][4], blf[2][4];
#pragma unroll
                    for (int npl = 0; npl < 2; npl++) {
                        int row = 16 * (2 * h + npl) + (lane & 7) + ((lane >> 4) << 3);
                        int ck  = 2 * kb + ((lane >> 3) & 1);
                        ldm_x4(bhf[npl], tb + P_KH + swzo(row, ck));
                        ldm_x4(blf[npl], tb + P_KL + swzo(row, ck));
                    }
                    // chain qh x kh over 4 targets
#pragma unroll
                    for (int npl = 0; npl < 2; npl++) {
                        mma16816(sa[2*npl],   qhf, bhf[npl][0], bhf[npl][1]);
                        mma16816(sa[2*npl+1], qhf, bhf[npl][2], bhf[npl][3]);
                    }
                    // chain ql x kh
#pragma unroll
                    for (int npl = 0; npl < 2; npl++) {
                        mma16816(sa[2*npl],   qlf, bhf[npl][0], bhf[npl][1]);
                        mma16816(sa[2*npl+1], qlf, bhf[npl][2], bhf[npl][3]);
                    }
                    // chain qh x kl
#pragma unroll
                    for (int npl = 0; npl < 2; npl++) {
                        mma16816(sa[2*npl],   qhf, blf[npl][0], blf[npl][1]);
                        mma16816(sa[2*npl+1], qhf, blf[npl][2], blf[npl][3]);
                    }
                }

                // ===== epilogue(half) =====
                uint32_t phf[2][4], plf[2][4];
#pragma unroll
                for (int nbl = 0; nbl < 4; nbl++) {
                    int n0 = 8 * (4 * h + nbl) + 2 * (lane & 3);
                    float p0, p1, p2, p3;
                    if (!partial) {
                        float c0 = ce[n0], c1 = ce[n0 + 1];
                        p0 = sa[nbl][0] * rr0 * c0; p1 = sa[nbl][1] * rr0 * c1;
                        p2 = sa[nbl][2] * rr1 * c0; p3 = sa[nbl][3] * rr1 * c1;
                    } else {
                        int s0g = kt * BN + n0;
                        float g0 = gg[n0], g1 = gg[n0 + 1];
                        p0 = (s0g     <= rowg0) ? sa[nbl][0] * __expf(g0 - cm0) : 0.f;
                        p1 = (s0g + 1 <= rowg0) ? sa[nbl][1] * __expf(g1 - cm0) : 0.f;
                        p2 = (s0g     <= rowg1) ? sa[nbl][2] * __expf(g0 - cm1) : 0.f;
                        p3 = (s0g + 1 <= rowg1) ? sa[nbl][3] * __expf(g1 - cm1) : 0.f;
                    }
                    rs0 += p0 + p1; rs1 += p2 + p3;
                    int kfl = nbl >> 1, hx = (nbl & 1) * 2;
                    split2f(p0, p1, phf[kfl][hx],     plf[kfl][hx]);
                    split2f(p2, p3, phf[kfl][hx + 1], plf[kfl][hx + 1]);
                }

                // ===== MMA2(half): H += P[:,32h:32h+32) . V[32h:32h+32,:] =====
#pragma unroll
                for (int kfl = 0; kfl < 2; kfl++) {
                    const int vrow0 = 16 * (2 * h + kfl) + (lane & 7)
                                    + (((lane >> 3) & 1) << 3);
#pragma unroll
                    for (int grp = 0; grp < 2; grp++) {
                        uint32_t vhf[4][4], vlf[4][4];
#pragma unroll
                        for (int j = 0; j < 4; j++) {
                            int np = grp * 4 + j;
                            int ck = 2 * np + (lane >> 4);
                            ldm_x4_t(vhf[j], tb + P_VH + swzo(vrow0, ck));
                            ldm_x4_t(vlf[j], tb + P_VL + swzo(vrow0, ck));
                        }
                        // chain ph x vh over 8 targets
#pragma unroll
                        for (int j = 0; j < 4; j++) {
                            int t = 8 * grp + 2 * j;
                            mma16816(hacc[t],   phf[kfl], vhf[j][0], vhf[j][1]);
                            mma16816(hacc[t+1], phf[kfl], vhf[j][2], vhf[j][3]);
                        }
                        // chain ph x vl
#pragma unroll
                        for (int j = 0; j < 4; j++) {
                            int t = 8 * grp + 2 * j;
                            mma16816(hacc[t],   phf[kfl], vlf[j][0], vlf[j][1]);
                            mma16816(hacc[t+1], phf[kfl], vlf[j][2], vlf[j][3]);
                        }
                        // chain pl x vh
#pragma unroll
                        for (int j = 0; j < 4; j++) {
                            int t = 8 * grp + 2 * j;
                            mma16816(hacc[t],   plf[kfl], vhf[j][0], vhf[j][1]);
                            mma16816(hacc[t+1], plf[kfl], vhf[j][2], vhf[j][3]);
                        }
                    }
                }
            }

            CP_WAIT0();
            __syncthreads();
        }

        // ---- reduce rowsums, normalize, write ----
        rs0 += __shfl_xor_sync(0xffffffffu, rs0, 1);
        rs0 += __shfl_xor_sync(0xffffffffu, rs0, 2);
        rs1 += __shfl_xor_sync(0xffffffffu, rs1, 1);
        rs1 += __shfl_xor_sync(0xffffffffu, rs1, 2);
        const float inv0 = 1.f / fmaxf(fabsf(rs0), nf0);
        const float inv1 = 1.f / fmaxf(fabsf(rs1), nf1);
        float* o0 = out + ((size_t)(bh * T_ + rowg0)) * KD;
        float* o1 = out + ((size_t)(bh * T_ + rowg1)) * KD;
#pragma unroll
        for (int nb = 0; nb < 16; nb++) {
            int c = 8 * nb + 2 * (lane & 3);
            *(float2*)(o0 + c) = make_float2(hacc[nb][0] * inv0, hacc[nb][1] * inv0);
            *(float2*)(o1 + c) = make_float2(hacc[nb][2] * inv1, hacc[nb][3] * inv1);
        }

        // ---- next task ----
        __syncthreads();
        if (tid == 0) sh_task = (int)atomicAdd(&d_task_ctr, 1u);
        __syncthreads();
        task = sh_task;
    }
}

// ---------------------------------------------------------------------------
extern "C" void kernel_launch(void* const* d_in, const int* in_sizes, int n_in,
                              void* d_out, int out_size) {
    const float* q  = (const float*)d_in[0];
    const float* k  = (const float*)d_in[1];
    const float* v  = (const float*)d_in[2];
    const float* ig = (const float*)d_in[3];
    const float* fg = (const float*)d_in[4];
    float* out = (float*)d_out;

    fused_pre<<<4096 + 16, 256>>>(k, v, ig, fg);

    cudaFuncSetAttribute(mlstm_mma,
                         cudaFuncAttributeMaxDynamicSharedMemorySize, SMEM_TOTAL);
    mlstm_mma<<<GRID_MAIN, 256, SMEM_TOTAL>>>(q, out);
}

// round 12
// speedup vs baseline: 1.0305x; 1.0305x over previous
#include <cuda_runtime.h>
#include <cuda_bf16.h>
#include <math.h>
#include <stdint.h>

#define B_  2
#define H_  8
#define T_  2048
#define KD  128
#define BH  (B_*H_)
#define BN  64
#define NKT (T_/BN)      // 32 kv tiles of 64
#define NQT (T_/128)     // 16 q tiles of 128
#define NTASK (BH*NQT)   // 256
#define NELEM (BH*T_*KD)
#define GRID_MAIN 148

// ---------------- device-global scratch -----------------------------------
__device__ float d_g [BH*T_];
__device__ float d_cm[BH*T_];
__device__ float d_nf[BH*T_];
__device__ float d_ce[BH*T_];
__device__ float d_Gt[BH*NKT];
__device__ unsigned int d_task_ctr;

__device__ __nv_bfloat16 d_kh[NELEM], d_kl[NELEM];
__device__ __nv_bfloat16 d_vh[NELEM], d_vl[NELEM];

// ---------------- helpers -------------------------------------------------
__device__ __forceinline__ uint32_t smem_u32(const void* p) {
    uint32_t a;
    asm("{ .reg .u64 t; cvta.to.shared.u64 t, %1; cvt.u32.u64 %0, t; }"
        : "=r"(a) : "l"(p));
    return a;
}

#define CP16(dst, src) \
    asm volatile("cp.async.cg.shared.global [%0], [%1], 16;" :: "r"(dst), "l"(src))
#define CP_COMMIT() asm volatile("cp.async.commit_group;" ::: "memory")
#define CP_WAIT0()  asm volatile("cp.async.wait_group 0;" ::: "memory")

__device__ __forceinline__ void ldm_x4(uint32_t* r, uint32_t addr) {
    asm volatile("ldmatrix.sync.aligned.m8n8.x4.shared.b16 {%0,%1,%2,%3}, [%4];"
        : "=r"(r[0]), "=r"(r[1]), "=r"(r[2]), "=r"(r[3]) : "r"(addr));
}
__device__ __forceinline__ void ldm_x4_t(uint32_t* r, uint32_t addr) {
    asm volatile("ldmatrix.sync.aligned.m8n8.x4.trans.shared.b16 {%0,%1,%2,%3}, [%4];"
        : "=r"(r[0]), "=r"(r[1]), "=r"(r[2]), "=r"(r[3]) : "r"(addr));
}
__device__ __forceinline__ void mma16816(float (&d)[4], const uint32_t (&a)[4],
                                         uint32_t b0, uint32_t b1) {
    asm volatile(
        "mma.sync.aligned.m16n8k16.row.col.f32.bf16.bf16.f32 "
        "{%0,%1,%2,%3}, {%4,%5,%6,%7}, {%8,%9}, {%0,%1,%2,%3};"
        : "+f"(d[0]), "+f"(d[1]), "+f"(d[2]), "+f"(d[3])
        : "r"(a[0]), "r"(a[1]), "r"(a[2]), "r"(a[3]), "r"(b0), "r"(b1));
}

// fast split: hi = truncate-to-bf16, lo = RN(x - hi)
__device__ __forceinline__ void split2f(float a, float b, uint32_t& h, uint32_t& l) {
    uint32_t ua = __float_as_uint(a) & 0xffff0000u;
    uint32_t ub = __float_as_uint(b) & 0xffff0000u;
    float la = a - __uint_as_float(ua);
    float lb = b - __uint_as_float(ub);
    h = (ua >> 16) | ub;
    __nv_bfloat162 p = __float22bfloat162_rn(make_float2(la, lb));
    l = *reinterpret_cast<uint32_t*>(&p);
}

// swizzled chunk offset: 16 chunks (16B) per 256B row
__device__ __forceinline__ uint32_t swzo(int row, int ck) {
    return (uint32_t)((row * 16 + (ck ^ (row & 7))) << 4);
}

// ---------------- smem layout (bytes) -------------------------------------
#define OFF_QH   0
#define OFF_QL   32768
#define OFF_TILE(b) (65536 + (b) * 65536)
#define P_KH 0
#define P_KL 16384
#define P_VH 32768
#define P_VL 49152
#define OFF_CE(b) (196608 + (b) * 256)
#define OFF_G(b)  (197120 + (b) * 256)
#define SMEM_TOTAL 197632

// ---------------------------------------------------------------------------
// Fused pre-pass. Blocks [0,16): per-head gate scan (FIRST, overlaps splat).
// Blocks [16,4112): split K/V into bf16 hi/lo planes.
// ---------------------------------------------------------------------------
__global__ void fused_pre(const float* __restrict__ k, const float* __restrict__ v,
                          const float* __restrict__ ig, const float* __restrict__ fg) {
    __shared__ double sh[256];
    __shared__ float shf[256];
    __shared__ float tm[32];
    const int tid = threadIdx.x;

    if (blockIdx.x >= 16) {
        int i = (blockIdx.x - 16) * 256 + tid;
        float4 kv = ((const float4*)k)[i];
        float4 vv = ((const float4*)v)[i];
        uint32_t h0, l0, h1, l1;
        split2f(kv.x, kv.y, h0, l0); split2f(kv.z, kv.w, h1, l1);
        ((uint2*)d_kh)[i] = make_uint2(h0, h1);
        ((uint2*)d_kl)[i] = make_uint2(l0, l1);
        split2f(vv.x, vv.y, h0, l0); split2f(vv.z, vv.w, h1, l1);
        ((uint2*)d_vh)[i] = make_uint2(h0, h1);
        ((uint2*)d_vl)[i] = make_uint2(l0, l1);
        return;
    }

    const int bh = blockIdx.x;
    if (bh == 0 && tid == 0) d_task_ctr = GRID_MAIN;
    const float* fp = fg + (size_t)bh * T_;
    const float* ip = ig + (size_t)bh * T_;
    const int base = tid * 8;

    double lf[8]; float gi[8];
#pragma unroll
    for (int r = 0; r < 8; r++) {
        float x = fp[base + r];
        lf[r] = (double)(fminf(x, 0.f) - log1pf(__expf(-fabsf(x))));
        gi[r] = ip[base + r];
    }
    double run = 0.0, fc[8];
#pragma unroll
    for (int r = 0; r < 8; r++) { run += lf[r]; fc[r] = run; }

    sh[tid] = run; __syncthreads();
    for (int off = 1; off < 256; off <<= 1) {
        double t = 0.0; if (tid >= off) t = sh[tid - off];
        __syncthreads();
        if (tid >= off) sh[tid] += t;
        __syncthreads();
    }
    double addoff = sh[tid] - run;

    double g[8], gm[8], runm = -1e300;
#pragma unroll
    for (int r = 0; r < 8; r++) {
        fc[r] += addoff;
        g[r]  = (double)gi[r] - fc[r];
        runm  = fmax(runm, g[r]);
        gm[r] = runm;
    }
    __syncthreads();
    sh[tid] = runm; __syncthreads();
    for (int off = 1; off < 256; off <<= 1) {
        double t = -1e300; if (tid >= off) t = sh[tid - off];
        __syncthreads();
        if (tid >= off) sh[tid] = fmax(sh[tid], t);
        __syncthreads();
    }
    double prevmax = (tid == 0) ? -1e300 : sh[tid - 1];

    float gf[8];
#pragma unroll
    for (int r = 0; r < 8; r++) {
        double cm = fmax(prevmax, gm[r]);
        gf[r] = (float)g[r];
        d_g [bh*T_ + base + r] = gf[r];
        d_cm[bh*T_ + base + r] = (float)cm;
        d_nf[bh*T_ + base + r] = __expf((float)(-(fc[r] + cm)));
    }

    float lmax = gf[0];
#pragma unroll
    for (int r = 1; r < 8; r++) lmax = fmaxf(lmax, gf[r]);
    __syncthreads();
    shf[tid] = lmax; __syncthreads();
    if (tid < 32) {
        float mx = shf[tid * 8];
#pragma unroll
        for (int u = 1; u < 8; u++) mx = fmaxf(mx, shf[tid * 8 + u]);
        tm[tid] = mx;
        d_Gt[bh*NKT + tid] = mx;
    }
    __syncthreads();
    float G = tm[tid >> 3];
#pragma unroll
    for (int r = 0; r < 8; r++)
        d_ce[bh*T_ + base + r] = __expf(gf[r] - G);
}

// ---------------------------------------------------------------------------
// tile loader: 64-row K/V bf16 planes + aux vectors, cp.async, 256 threads
// ---------------------------------------------------------------------------
__device__ __forceinline__ void load_tile(uint32_t sb, int b, int bh, int kt, int tid) {
    size_t gbase = ((size_t)(bh * T_ + kt * BN)) * KD;
    const char* gkh = (const char*)d_kh + gbase * 2;
    const char* gkl = (const char*)d_kl + gbase * 2;
    const char* gvh = (const char*)d_vh + gbase * 2;
    const char* gvl = (const char*)d_vl + gbase * 2;
    uint32_t tb = sb + OFF_TILE(b);
#pragma unroll
    for (int u = 0; u < 4; u++) {
        int ch = tid + u * 256;
        int r = ch >> 4, c = ch & 15;
        uint32_t a = swzo(r, c);
        size_t go = (size_t)ch * 16;
        CP16(tb + P_KH + a, gkh + go);
        CP16(tb + P_KL + a, gkl + go);
        CP16(tb + P_VH + a, gvh + go);
        CP16(tb + P_VL + a, gvl + go);
    }
    if (tid < 16) {
        CP16(sb + OFF_CE(b) + tid * 16,
             (const char*)(d_ce + bh * T_ + kt * BN) + tid * 16);
    } else if (tid < 32) {
        CP16(sb + OFF_G(b) + (tid - 16) * 16,
             (const char*)(d_g + bh * T_ + kt * BN) + (tid - 16) * 16);
    }
}

// ---------------------------------------------------------------------------
// Main kernel: 256 threads (8 warps), BM=128, BN=64, persistent queue,
// Q fragments register-resident, chain-major MMA (distance 8), LDSM/MMA
// interleaved so B-plane loads hide under ready-operand chains.
// ---------------------------------------------------------------------------
__global__ void __launch_bounds__(256, 1)
mlstm_mma(const float* __restrict__ q, float* __restrict__ out) {
    extern __shared__ char smem[];
    __shared__ int sh_task;
    const uint32_t sb = smem_u32(smem);
    const int tid  = threadIdx.x;
    const int lane = tid & 31;
    const int wid  = tid >> 5;
    const int m0   = wid * 16;
    const float scale = 0.08838834764831845f; // 128^-0.5

    int task = blockIdx.x;
    for (;;) {
        if (task >= NTASK) return;
        const int bh = task & 15;
        const int qt = (NQT - 1) - (task >> 4);    // descending work
        const int NT = 2 * qt + 2;
        const int q0 = qt * 128;

        // kick tile 0 fetch first, then stage Q planes (disjoint smem)
        load_tile(sb, 0, bh, 0, tid);
        CP_COMMIT();

        const float* qbase = q + (size_t)(bh * T_ + q0) * KD;
#pragma unroll
        for (int u = 0; u < 8; u++) {
            int ch = tid + u * 256;
            int r = ch >> 4, c = ch & 15;
            const float4* src = (const float4*)(qbase + r * 128 + c * 8);
            float4 x0 = src[0], x1 = src[1];
            uint32_t h0, l0, h1, l1, h2, l2, h3, l3;
            split2f(x0.x * scale, x0.y * scale, h0, l0);
            split2f(x0.z * scale, x0.w * scale, h1, l1);
            split2f(x1.x * scale, x1.y * scale, h2, l2);
            split2f(x1.z * scale, x1.w * scale, h3, l3);
            uint32_t a = swzo(r, c);
            *(uint4*)(smem + OFF_QH + a) = make_uint4(h0, h1, h2, h3);
            *(uint4*)(smem + OFF_QL + a) = make_uint4(l0, l1, l2, l3);
        }

        const int rowg0 = q0 + m0 + (lane >> 2);
        const int rowg1 = rowg0 + 8;
        const float cm0 = d_cm[bh * T_ + rowg0];
        const float cm1 = d_cm[bh * T_ + rowg1];
        const float nf0 = d_nf[bh * T_ + rowg0];
        const float nf1 = d_nf[bh * T_ + rowg1];

        float hacc[16][4];
#pragma unroll
        for (int i = 0; i < 16; i++)
#pragma unroll
            for (int j = 0; j < 4; j++) hacc[i][j] = 0.f;
        float rs0 = 0.f, rs1 = 0.f;

        CP_WAIT0();
        __syncthreads();          // Q planes + tile 0 + aux 0 all visible

        // ---- Q fragments -> registers (once per task) ----
        uint32_t qh[8][4], ql[8][4];
#pragma unroll
        for (int kb = 0; kb < 8; kb++) {
            int row = m0 + (lane & 15);
            int ck  = 2 * kb + (lane >> 4);
            ldm_x4(qh[kb], sb + OFF_QH + swzo(row, ck));
            ldm_x4(ql[kb], sb + OFF_QL + swzo(row, ck));
        }

        for (int kt = 0; kt < NT; kt++) {
            const int b = kt & 1;
            if (kt + 1 < NT) { load_tile(sb, 1 - b, bh, kt + 1, tid); CP_COMMIT(); }
            const uint32_t tb = sb + OFF_TILE(b);
            const float Gtv = __ldg(&d_Gt[bh * NKT + kt]);

            const int  smin = kt * BN;
            const int  wmrow = q0 + m0;
            const bool fullmask = (smin > wmrow + 15);
            const bool partial  = !fullmask && (smin + BN - 1 > wmrow);

            if (!fullmask) {
                // ================= MMA1: S = Qs.K^T =========================
                float sa[8][4];
#pragma unroll
                for (int i = 0; i < 8; i++)
#pragma unroll
                    for (int j = 0; j < 4; j++) sa[i][j] = 0.f;

#pragma unroll
                for (int kb = 0; kb < 8; kb++) {
                    const int brow = (lane & 7) + ((lane >> 4) << 3);
                    const int bck  = 2 * kb + ((lane >> 3) & 1);
                    uint32_t bhf[4][4];
#pragma unroll
                    for (int np = 0; np < 4; np++)
                        ldm_x4(bhf[np], tb + P_KH + swzo(16 * np + brow, bck));
                    // chain qh x kh (operands ready) while kl loads
#pragma unroll
                    for (int np = 0; np < 4; np++) {
                        mma16816(sa[2*np],   qh[kb], bhf[np][0], bhf[np][1]);
                        mma16816(sa[2*np+1], qh[kb], bhf[np][2], bhf[np][3]);
                    }
                    uint32_t blf[4][4];
#pragma unroll
                    for (int np = 0; np < 4; np++)
                        ldm_x4(blf[np], tb + P_KL + swzo(16 * np + brow, bck));
                    // chain ql x kh
#pragma unroll
                    for (int np = 0; np < 4; np++) {
                        mma16816(sa[2*np],   ql[kb], bhf[np][0], bhf[np][1]);
                        mma16816(sa[2*np+1], ql[kb], bhf[np][2], bhf[np][3]);
                    }
                    // chain qh x kl
#pragma unroll
                    for (int np = 0; np < 4; np++) {
                        mma16816(sa[2*np],   qh[kb], blf[np][0], blf[np][1]);
                        mma16816(sa[2*np+1], qh[kb], blf[np][2], blf[np][3]);
                    }
                }

                // ================= epilogue =================================
                const float* ce = (const float*)(smem + OFF_CE(b));
                const float* gg = (const float*)(smem + OFF_G(b));
                const float rr0 = __expf(Gtv - cm0);
                const float rr1 = __expf(Gtv - cm1);
                uint32_t phf[4][4], plf[4][4];
#pragma unroll
                for (int nb = 0; nb < 8; nb++) {
                    int n0 = 8 * nb + 2 * (lane & 3);
                    float p0, p1, p2, p3;
                    if (!partial) {
                        float c0 = ce[n0], c1 = ce[n0 + 1];
                        p0 = sa[nb][0] * rr0 * c0; p1 = sa[nb][1] * rr0 * c1;
                        p2 = sa[nb][2] * rr1 * c0; p3 = sa[nb][3] * rr1 * c1;
                    } else {
                        int s0g = smin + n0;
                        float g0 = gg[n0], g1 = gg[n0 + 1];
                        p0 = (s0g     <= rowg0) ? sa[nb][0] * __expf(g0 - cm0) : 0.f;
                        p1 = (s0g + 1 <= rowg0) ? sa[nb][1] * __expf(g1 - cm0) : 0.f;
                        p2 = (s0g     <= rowg1) ? sa[nb][2] * __expf(g0 - cm1) : 0.f;
                        p3 = (s0g + 1 <= rowg1) ? sa[nb][3] * __expf(g1 - cm1) : 0.f;
                    }
                    rs0 += p0 + p1; rs1 += p2 + p3;
                    int kf = nb >> 1, hx = (nb & 1) * 2;
                    split2f(p0, p1, phf[kf][hx],     plf[kf][hx]);
                    split2f(p2, p3, phf[kf][hx + 1], plf[kf][hx + 1]);
                }

                // ================= MMA2: H += P.V ===========================
#pragma unroll
                for (int kf = 0; kf < 4; kf++) {
                    const int vrow = 16 * kf + (lane & 7) + (((lane >> 3) & 1) << 3);
#pragma unroll
                    for (int grp = 0; grp < 2; grp++) {
                        uint32_t vhf[4][4];
#pragma unroll
                        for (int j = 0; j < 4; j++) {
                            int ck = 2 * (grp * 4 + j) + (lane >> 4);
                            ldm_x4_t(vhf[j], tb + P_VH + swzo(vrow, ck));
                        }
                        // chain ph x vh (ready) while vl loads
#pragma unroll
                        for (int j = 0; j < 4; j++) {
                            int t = 8 * grp + 2 * j;
                            mma16816(hacc[t],   phf[kf], vhf[j][0], vhf[j][1]);
                            mma16816(hacc[t+1], phf[kf], vhf[j][2], vhf[j][3]);
                        }
                        uint32_t vlf[4][4];
#pragma unroll
                        for (int j = 0; j < 4; j++) {
                            int ck = 2 * (grp * 4 + j) + (lane >> 4);
                            ldm_x4_t(vlf[j], tb + P_VL + swzo(vrow, ck));
                        }
                        // chain ph x vl
#pragma unroll
                        for (int j = 0; j < 4; j++) {
                            int t = 8 * grp + 2 * j;
                            mma16816(hacc[t],   phf[kf], vlf[j][0], vlf[j][1]);
                            mma16816(hacc[t+1], phf[kf], vlf[j][2], vlf[j][3]);
                        }
                        // chain pl x vh
#pragma unroll
                        for (int j = 0; j < 4; j++) {
                            int t = 8 * grp + 2 * j;
                            mma16816(hacc[t],   plf[kf], vhf[j][0], vhf[j][1]);
                            mma16816(hacc[t+1], plf[kf], vhf[j][2], vhf[j][3]);
                        }
                    }
                }
            }

            CP_WAIT0();
            __syncthreads();
        }

        // ---- reduce rowsums, normalize, write ----
        rs0 += __shfl_xor_sync(0xffffffffu, rs0, 1);
        rs0 += __shfl_xor_sync(0xffffffffu, rs0, 2);
        rs1 += __shfl_xor_sync(0xffffffffu, rs1, 1);
        rs1 += __shfl_xor_sync(0xffffffffu, rs1, 2);
        const float inv0 = 1.f / fmaxf(fabsf(rs0), nf0);
        const float inv1 = 1.f / fmaxf(fabsf(rs1), nf1);
        float* o0 = out + ((size_t)(bh * T_ + rowg0)) * KD;
        float* o1 = out + ((size_t)(bh * T_ + rowg1)) * KD;
#pragma unroll
        for (int nb = 0; nb < 16; nb++) {
            int c = 8 * nb + 2 * (lane & 3);
            *(float2*)(o0 + c) = make_float2(hacc[nb][0] * inv0, hacc[nb][1] * inv0);
            *(float2*)(o1 + c) = make_float2(hacc[nb][2] * inv1, hacc[nb][3] * inv1);
        }

        // ---- next task ----
        __syncthreads();
        if (tid == 0) sh_task = (int)atomicAdd(&d_task_ctr, 1u);
        __syncthreads();
        task = sh_task;
    }
}

// ---------------------------------------------------------------------------
extern "C" void kernel_launch(void* const* d_in, const int* in_sizes, int n_in,
                              void* d_out, int out_size) {
    const float* q  = (const float*)d_in[0];
    const float* k  = (const float*)d_in[1];
    const float* v  = (const float*)d_in[2];
    const float* ig = (const float*)d_in[3];
    const float* fg = (const float*)d_in[4];
    float* out = (float*)d_out;

    fused_pre<<<4096 + 16, 256>>>(k, v, ig, fg);

    cudaFuncSetAttribute(mlstm_mma,
                         cudaFuncAttributeMaxDynamicSharedMemorySize, SMEM_TOTAL);
    mlstm_mma<<<GRID_MAIN, 256, SMEM_TOTAL>>>(q, out);
}

// round 13
// speedup vs baseline: 1.1370x; 1.1033x over previous
#include <cuda_runtime.h>
#include <cuda_bf16.h>
#include <math.h>
#include <stdint.h>

#define B_  2
#define H_  8
#define T_  2048
#define KD  128
#define BH  (B_*H_)
#define BN  64
#define NKT (T_/BN)      // 32 kv tiles of 64
#define NQT (T_/128)     // 16 q tiles of 128
#define NTASK (BH*NQT)   // 256
#define NELEM (BH*T_*KD)
#define GRID_MAIN 148

// ---------------- device-global scratch -----------------------------------
__device__ float d_g [BH*T_];
__device__ float d_cm[BH*T_];
__device__ float d_nf[BH*T_];
__device__ float d_ce[BH*T_];
__device__ float d_Gt[BH*NKT];
__device__ unsigned int d_task_ctr;

__device__ __nv_bfloat16 d_kh[NELEM], d_kl[NELEM];
__device__ __nv_bfloat16 d_vh[NELEM], d_vl[NELEM];

// ---------------- helpers -------------------------------------------------
__device__ __forceinline__ uint32_t smem_u32(const void* p) {
    uint32_t a;
    asm("{ .reg .u64 t; cvta.to.shared.u64 t, %1; cvt.u32.u64 %0, t; }"
        : "=r"(a) : "l"(p));
    return a;
}

#define CP16(dst, src) \
    asm volatile("cp.async.cg.shared.global [%0], [%1], 16;" :: "r"(dst), "l"(src))

#define MBAR_INIT(a, c) \
    asm volatile("mbarrier.init.shared.b64 [%0], %1;" :: "r"(a), "r"(c) : "memory")
#define MBAR_ARRIVE(a) \
    asm volatile("mbarrier.arrive.shared.b64 _, [%0];" :: "r"(a) : "memory")
#define CP_MBAR_ARRIVE(a) \
    asm volatile("cp.async.mbarrier.arrive.noinc.shared.b64 [%0];" :: "r"(a) : "memory")

__device__ __forceinline__ void mbar_wait(uint32_t a, uint32_t parity) {
    asm volatile(
        "{\n\t.reg .pred P;\n\t"
        "WL_%=:\n\t"
        "mbarrier.try_wait.parity.shared.b64 P, [%0], %1;\n\t"
        "@P bra.uni WD_%=;\n\t"
        "bra.uni WL_%=;\n\t"
        "WD_%=:\n\t}"
        :: "r"(a), "r"(parity) : "memory");
}

__device__ __forceinline__ void ldm_x4(uint32_t* r, uint32_t addr) {
    asm volatile("ldmatrix.sync.aligned.m8n8.x4.shared.b16 {%0,%1,%2,%3}, [%4];"
        : "=r"(r[0]), "=r"(r[1]), "=r"(r[2]), "=r"(r[3]) : "r"(addr));
}
__device__ __forceinline__ void ldm_x4_t(uint32_t* r, uint32_t addr) {
    asm volatile("ldmatrix.sync.aligned.m8n8.x4.trans.shared.b16 {%0,%1,%2,%3}, [%4];"
        : "=r"(r[0]), "=r"(r[1]), "=r"(r[2]), "=r"(r[3]) : "r"(addr));
}
__device__ __forceinline__ void mma16816(float (&d)[4], const uint32_t (&a)[4],
                                         uint32_t b0, uint32_t b1) {
    asm volatile(
        "mma.sync.aligned.m16n8k16.row.col.f32.bf16.bf16.f32 "
        "{%0,%1,%2,%3}, {%4,%5,%6,%7}, {%8,%9}, {%0,%1,%2,%3};"
        : "+f"(d[0]), "+f"(d[1]), "+f"(d[2]), "+f"(d[3])
        : "r"(a[0]), "r"(a[1]), "r"(a[2]), "r"(a[3]), "r"(b0), "r"(b1));
}

// fast split: hi = truncate-to-bf16, lo = RN(x - hi)
__device__ __forceinline__ void split2f(float a, float b, uint32_t& h, uint32_t& l) {
    uint32_t ua = __float_as_uint(a) & 0xffff0000u;
    uint32_t ub = __float_as_uint(b) & 0xffff0000u;
    float la = a - __uint_as_float(ua);
    float lb = b - __uint_as_float(ub);
    h = (ua >> 16) | ub;
    __nv_bfloat162 p = __float22bfloat162_rn(make_float2(la, lb));
    l = *reinterpret_cast<uint32_t*>(&p);
}

// swizzled chunk offset: 16 chunks (16B) per 256B row
__device__ __forceinline__ uint32_t swzo(int row, int ck) {
    return (uint32_t)((row * 16 + (ck ^ (row & 7))) << 4);
}

// ---------------- smem layout (bytes) -------------------------------------
// 3 pipeline stages; Q staging transiently borrows the first stage's tile
// area at task start (Q fragments live in registers during the mainloop).
#define STG_SZ 66560
#define STG(s) ((s) * STG_SZ)
#define P_KH 0
#define P_KL 16384
#define P_VH 32768
#define P_VL 49152
#define A_CE 65536
#define A_G  65792
#define MB_OFF (3 * STG_SZ)              // 199680
#define MB_EMPTY(s) (MB_OFF + (s) * 16)
#define MB_FULL(s)  (MB_OFF + (s) * 16 + 8)
#define SMEM_TOTAL (MB_OFF + 128)

// ---------------------------------------------------------------------------
// Fused pre-pass. Blocks [0,16): per-head gate scan (FIRST, overlaps splat).
// Blocks [16,4112): split K/V into bf16 hi/lo planes.
// ---------------------------------------------------------------------------
__global__ void fused_pre(const float* __restrict__ k, const float* __restrict__ v,
                          const float* __restrict__ ig, const float* __restrict__ fg) {
    __shared__ double sh[256];
    __shared__ float shf[256];
    __shared__ float tm[32];
    const int tid = threadIdx.x;

    if (blockIdx.x >= 16) {
        int i = (blockIdx.x - 16) * 256 + tid;
        float4 kv = ((const float4*)k)[i];
        float4 vv = ((const float4*)v)[i];
        uint32_t h0, l0, h1, l1;
        split2f(kv.x, kv.y, h0, l0); split2f(kv.z, kv.w, h1, l1);
        ((uint2*)d_kh)[i] = make_uint2(h0, h1);
        ((uint2*)d_kl)[i] = make_uint2(l0, l1);
        split2f(vv.x, vv.y, h0, l0); split2f(vv.z, vv.w, h1, l1);
        ((uint2*)d_vh)[i] = make_uint2(h0, h1);
        ((uint2*)d_vl)[i] = make_uint2(l0, l1);
        return;
    }

    const int bh = blockIdx.x;
    if (bh == 0 && tid == 0) d_task_ctr = GRID_MAIN;
    const float* fp = fg + (size_t)bh * T_;
    const float* ip = ig + (size_t)bh * T_;
    const int base = tid * 8;

    double lf[8]; float gi[8];
#pragma unroll
    for (int r = 0; r < 8; r++) {
        float x = fp[base + r];
        lf[r] = (double)(fminf(x, 0.f) - log1pf(__expf(-fabsf(x))));
        gi[r] = ip[base + r];
    }
    double run = 0.0, fc[8];
#pragma unroll
    for (int r = 0; r < 8; r++) { run += lf[r]; fc[r] = run; }

    sh[tid] = run; __syncthreads();
    for (int off = 1; off < 256; off <<= 1) {
        double t = 0.0; if (tid >= off) t = sh[tid - off];
        __syncthreads();
        if (tid >= off) sh[tid] += t;
        __syncthreads();
    }
    double addoff = sh[tid] - run;

    double g[8], gm[8], runm = -1e300;
#pragma unroll
    for (int r = 0; r < 8; r++) {
        fc[r] += addoff;
        g[r]  = (double)gi[r] - fc[r];
        runm  = fmax(runm, g[r]);
        gm[r] = runm;
    }
    __syncthreads();
    sh[tid] = runm; __syncthreads();
    for (int off = 1; off < 256; off <<= 1) {
        double t = -1e300; if (tid >= off) t = sh[tid - off];
        __syncthreads();
        if (tid >= off) sh[tid] = fmax(sh[tid], t);
        __syncthreads();
    }
    double prevmax = (tid == 0) ? -1e300 : sh[tid - 1];

    float gf[8];
#pragma unroll
    for (int r = 0; r < 8; r++) {
        double cm = fmax(prevmax, gm[r]);
        gf[r] = (float)g[r];
        d_g [bh*T_ + base + r] = gf[r];
        d_cm[bh*T_ + base + r] = (float)cm;
        d_nf[bh*T_ + base + r] = __expf((float)(-(fc[r] + cm)));
    }

    float lmax = gf[0];
#pragma unroll
    for (int r = 1; r < 8; r++) lmax = fmaxf(lmax, gf[r]);
    __syncthreads();
    shf[tid] = lmax; __syncthreads();
    if (tid < 32) {
        float mx = shf[tid * 8];
#pragma unroll
        for (int u = 1; u < 8; u++) mx = fmaxf(mx, shf[tid * 8 + u]);
        tm[tid] = mx;
        d_Gt[bh*NKT + tid] = mx;
    }
    __syncthreads();
    float G = tm[tid >> 3];
#pragma unroll
    for (int r = 0; r < 8; r++)
        d_ce[bh*T_ + base + r] = __expf(gf[r] - G);
}

// ---------------------------------------------------------------------------
// stage loader: K/V bf16 planes + aux into pipeline stage s (cp.async)
// ---------------------------------------------------------------------------
__device__ __forceinline__ void load_stage(uint32_t sb, int s, int bh, int kt, int tid) {
    size_t gbase = ((size_t)(bh * T_ + kt * BN)) * KD;
    const char* gkh = (const char*)d_kh + gbase * 2;
    const char* gkl = (const char*)d_kl + gbase * 2;
    const char* gvh = (const char*)d_vh + gbase * 2;
    const char* gvl = (const char*)d_vl + gbase * 2;
    uint32_t tb = sb + STG(s);
#pragma unroll
    for (int u = 0; u < 4; u++) {
        int ch = tid + u * 256;
        int r = ch >> 4, c = ch & 15;
        uint32_t a = swzo(r, c);
        size_t go = (size_t)ch * 16;
        CP16(tb + P_KH + a, gkh + go);
        CP16(tb + P_KL + a, gkl + go);
        CP16(tb + P_VH + a, gvh + go);
        CP16(tb + P_VL + a, gvl + go);
    }
    if (tid < 16) {
        CP16(tb + A_CE + tid * 16,
             (const char*)(d_ce + bh * T_ + kt * BN) + tid * 16);
    } else if (tid < 32) {
        CP16(tb + A_G + (tid - 16) * 16,
             (const char*)(d_g + bh * T_ + kt * BN) + (tid - 16) * 16);
    }
}

// ---------------------------------------------------------------------------
// Main kernel: 256 threads (8 warps), BM=128, BN=64, persistent queue.
// mbarrier-managed 3-stage tile pipeline, NO per-iteration __syncthreads —
// warps drift apart so LDSM bursts and MMA bursts overlap across warps.
// ---------------------------------------------------------------------------
__global__ void __launch_bounds__(256, 1)
mlstm_mma(const float* __restrict__ q, float* __restrict__ out) {
    extern __shared__ char smem[];
    __shared__ int sh_task;
    const uint32_t sb = smem_u32(smem);
    const int tid  = threadIdx.x;
    const int lane = tid & 31;
    const int wid  = tid >> 5;
    const int m0   = wid * 16;
    const float scale = 0.08838834764831845f; // 128^-0.5

    // pipeline barriers (persistent across tasks)
    if (tid == 0) {
#pragma unroll
        for (int s = 0; s < 3; s++) {
            MBAR_INIT(sb + MB_EMPTY(s), 256);
            MBAR_INIT(sb + MB_FULL(s), 256);
        }
    }
    __syncthreads();

    // cursors (identical across threads: same task stream)
    int pst = 0, pph = 1;   // producer: first empty-wait passes
    int cst = 0, cph = 0;   // consumer

    int task = blockIdx.x;
    for (;;) {
        if (task >= NTASK) return;
        const int bh = task & 15;
        const int qt = (NQT - 1) - (task >> 4);    // descending work
        const int NT = 2 * qt + 2;
        const int q0 = qt * 128;

        // ---- stage Q planes through stage pst's tile area (transient) ----
        __syncthreads();   // (A) all consumption arrives done; stage safe
        {
            const uint32_t qb = sb + STG(pst);
            const float* qbase = q + (size_t)(bh * T_ + q0) * KD;
#pragma unroll
            for (int u = 0; u < 8; u++) {
                int ch = tid + u * 256;
                int r = ch >> 4, c = ch & 15;
                const float4* src = (const float4*)(qbase + r * 128 + c * 8);
                float4 x0 = src[0], x1 = src[1];
                uint32_t h0, l0, h1, l1, h2, l2, h3, l3;
                split2f(x0.x * scale, x0.y * scale, h0, l0);
                split2f(x0.z * scale, x0.w * scale, h1, l1);
                split2f(x1.x * scale, x1.y * scale, h2, l2);
                split2f(x1.z * scale, x1.w * scale, h3, l3);
                uint32_t a = swzo(r, c);
                *(uint4*)(smem + STG(pst) + 0     + a) = make_uint4(h0, h1, h2, h3);
                *(uint4*)(smem + STG(pst) + 32768 + a) = make_uint4(l0, l1, l2, l3);
            }
            __syncthreads();   // (B) Q planes visible

            // Q fragments -> registers (once per task)
        }
        uint32_t qh[8][4], ql[8][4];
#pragma unroll
        for (int kb = 0; kb < 8; kb++) {
            int row = m0 + (lane & 15);
            int ck  = 2 * kb + (lane >> 4);
            ldm_x4(qh[kb], sb + STG(pst) + 0     + swzo(row, ck));
            ldm_x4(ql[kb], sb + STG(pst) + 32768 + swzo(row, ck));
        }
        __syncthreads();   // (C) everyone done reading Q; stage reusable

        // ---- producer: issue tile 0 ----
        mbar_wait(sb + MB_EMPTY(pst), (uint32_t)pph);
        load_stage(sb, pst, bh, 0, tid);
        CP_MBAR_ARRIVE(sb + MB_FULL(pst));
        if (++pst == 3) { pst = 0; pph ^= 1; }

        const int rowg0 = q0 + m0 + (lane >> 2);
        const int rowg1 = rowg0 + 8;
        const float cm0 = d_cm[bh * T_ + rowg0];
        const float cm1 = d_cm[bh * T_ + rowg1];
        const float nf0 = d_nf[bh * T_ + rowg0];
        const float nf1 = d_nf[bh * T_ + rowg1];

        float hacc[16][4];
#pragma unroll
        for (int i = 0; i < 16; i++)
#pragma unroll
            for (int j = 0; j < 4; j++) hacc[i][j] = 0.f;
        float rs0 = 0.f, rs1 = 0.f;

        for (int kt = 0; kt < NT; kt++) {
            // ---- producer: prefetch tile kt+1 ----
            if (kt + 1 < NT) {
                mbar_wait(sb + MB_EMPTY(pst), (uint32_t)pph);
                load_stage(sb, pst, bh, kt + 1, tid);
                CP_MBAR_ARRIVE(sb + MB_FULL(pst));
                if (++pst == 3) { pst = 0; pph ^= 1; }
            }

            // ---- consumer: wait tile kt ----
            mbar_wait(sb + MB_FULL(cst), (uint32_t)cph);
            const uint32_t tb = sb + STG(cst);
            const float Gtv = __ldg(&d_Gt[bh * NKT + kt]);

            const int  smin = kt * BN;
            const int  wmrow = q0 + m0;
            const bool fullmask = (smin > wmrow + 15);
            const bool partial  = !fullmask && (smin + BN - 1 > wmrow);

            if (!fullmask) {
                // ================= MMA1: S = Qs.K^T =========================
                float sa[8][4];
#pragma unroll
                for (int i = 0; i < 8; i++)
#pragma unroll
                    for (int j = 0; j < 4; j++) sa[i][j] = 0.f;

#pragma unroll
                for (int kb = 0; kb < 8; kb++) {
                    const int brow = (lane & 7) + ((lane >> 4) << 3);
                    const int bck  = 2 * kb + ((lane >> 3) & 1);
                    uint32_t bhf[4][4];
#pragma unroll
                    for (int np = 0; np < 4; np++)
                        ldm_x4(bhf[np], tb + P_KH + swzo(16 * np + brow, bck));
#pragma unroll
                    for (int np = 0; np < 4; np++) {
                        mma16816(sa[2*np],   qh[kb], bhf[np][0], bhf[np][1]);
                        mma16816(sa[2*np+1], qh[kb], bhf[np][2], bhf[np][3]);
                    }
                    uint32_t blf[4][4];
#pragma unroll
                    for (int np = 0; np < 4; np++)
                        ldm_x4(blf[np], tb + P_KL + swzo(16 * np + brow, bck));
#pragma unroll
                    for (int np = 0; np < 4; np++) {
                        mma16816(sa[2*np],   ql[kb], bhf[np][0], bhf[np][1]);
                        mma16816(sa[2*np+1], ql[kb], bhf[np][2], bhf[np][3]);
                    }
#pragma unroll
                    for (int np = 0; np < 4; np++) {
                        mma16816(sa[2*np],   qh[kb], blf[np][0], blf[np][1]);
                        mma16816(sa[2*np+1], qh[kb], blf[np][2], blf[np][3]);
                    }
                }

                // ================= epilogue =================================
                const float* ce = (const float*)(smem + STG(cst) + A_CE);
                const float* gg = (const float*)(smem + STG(cst) + A_G);
                const float rr0 = __expf(Gtv - cm0);
                const float rr1 = __expf(Gtv - cm1);
                uint32_t phf[4][4], plf[4][4];
#pragma unroll
                for (int nb = 0; nb < 8; nb++) {
                    int n0 = 8 * nb + 2 * (lane & 3);
                    float p0, p1, p2, p3;
                    if (!partial) {
                        float c0 = ce[n0], c1 = ce[n0 + 1];
                        p0 = sa[nb][0] * rr0 * c0; p1 = sa[nb][1] * rr0 * c1;
                        p2 = sa[nb][2] * rr1 * c0; p3 = sa[nb][3] * rr1 * c1;
                    } else {
                        int s0g = smin + n0;
                        float g0 = gg[n0], g1 = gg[n0 + 1];
                        p0 = (s0g     <= rowg0) ? sa[nb][0] * __expf(g0 - cm0) : 0.f;
                        p1 = (s0g + 1 <= rowg0) ? sa[nb][1] * __expf(g1 - cm0) : 0.f;
                        p2 = (s0g     <= rowg1) ? sa[nb][2] * __expf(g0 - cm1) : 0.f;
                        p3 = (s0g + 1 <= rowg1) ? sa[nb][3] * __expf(g1 - cm1) : 0.f;
                    }
                    rs0 += p0 + p1; rs1 += p2 + p3;
                    int kf = nb >> 1, hx = (nb & 1) * 2;
                    split2f(p0, p1, phf[kf][hx],     plf[kf][hx]);
                    split2f(p2, p3, phf[kf][hx + 1], plf[kf][hx + 1]);
                }

                // ================= MMA2: H += P.V ===========================
#pragma unroll
                for (int kf = 0; kf < 4; kf++) {
                    const int vrow = 16 * kf + (lane & 7) + (((lane >> 3) & 1) << 3);
#pragma unroll
                    for (int grp = 0; grp < 2; grp++) {
                        uint32_t vhf[4][4];
#pragma unroll
                        for (int j = 0; j < 4; j++) {
                            int ck = 2 * (grp * 4 + j) + (lane >> 4);
                            ldm_x4_t(vhf[j], tb + P_VH + swzo(vrow, ck));
                        }
#pragma unroll
                        for (int j = 0; j < 4; j++) {
                            int t = 8 * grp + 2 * j;
                            mma16816(hacc[t],   phf[kf], vhf[j][0], vhf[j][1]);
                            mma16816(hacc[t+1], phf[kf], vhf[j][2], vhf[j][3]);
                        }
                        uint32_t vlf[4][4];
#pragma unroll
                        for (int j = 0; j < 4; j++) {
                            int ck = 2 * (grp * 4 + j) + (lane >> 4);
                            ldm_x4_t(vlf[j], tb + P_VL + swzo(vrow, ck));
                        }
#pragma unroll
                        for (int j = 0; j < 4; j++) {
                            int t = 8 * grp + 2 * j;
                            mma16816(hacc[t],   phf[kf], vlf[j][0], vlf[j][1]);
                            mma16816(hacc[t+1], phf[kf], vlf[j][2], vlf[j][3]);
                        }
#pragma unroll
                        for (int j = 0; j < 4; j++) {
                            int t = 8 * grp + 2 * j;
                            mma16816(hacc[t],   plf[kf], vhf[j][0], vhf[j][1]);
                            mma16816(hacc[t+1], plf[kf], vhf[j][2], vhf[j][3]);
                        }
                    }
                }
            }

            // ---- consumer: release tile kt ----
            MBAR_ARRIVE(sb + MB_EMPTY(cst));
            if (++cst == 3) { cst = 0; cph ^= 1; }
        }

        // ---- reduce rowsums, normalize, write ----
        rs0 += __shfl_xor_sync(0xffffffffu, rs0, 1);
        rs0 += __shfl_xor_sync(0xffffffffu, rs0, 2);
        rs1 += __shfl_xor_sync(0xffffffffu, rs1, 1);
        rs1 += __shfl_xor_sync(0xffffffffu, rs1, 2);
        const float inv0 = 1.f / fmaxf(fabsf(rs0), nf0);
        const float inv1 = 1.f / fmaxf(fabsf(rs1), nf1);
        float* o0 = out + ((size_t)(bh * T_ + rowg0)) * KD;
        float* o1 = out + ((size_t)(bh * T_ + rowg1)) * KD;
#pragma unroll
        for (int nb = 0; nb < 16; nb++) {
            int c = 8 * nb + 2 * (lane & 3);
            *(float2*)(o0 + c) = make_float2(hacc[nb][0] * inv0, hacc[nb][1] * inv0);
            *(float2*)(o1 + c) = make_float2(hacc[nb][2] * inv1, hacc[nb][3] * inv1);
        }

        // ---- next task ----
        if (tid == 0) sh_task = (int)atomicAdd(&d_task_ctr, 1u);
        __syncthreads();
        task = sh_task;
    }
}

// ---------------------------------------------------------------------------
extern "C" void kernel_launch(void* const* d_in, const int* in_sizes, int n_in,
                              void* d_out, int out_size) {
    const float* q  = (const float*)d_in[0];
    const float* k  = (const float*)d_in[1];
    const float* v  = (const float*)d_in[2];
    const float* ig = (const float*)d_in[3];
    const float* fg = (const float*)d_in[4];
    float* out = (float*)d_out;

    fused_pre<<<4096 + 16, 256>>>(k, v, ig, fg);

    cudaFuncSetAttribute(mlstm_mma,
                         cudaFuncAttributeMaxDynamicSharedMemorySize, SMEM_TOTAL);
    mlstm_mma<<<GRID_MAIN, 256, SMEM_TOTAL>>>(q, out);
}

// round 15
// speedup vs baseline: 1.1408x; 1.0034x over previous
#include <cuda_runtime.h>
#include <cuda_bf16.h>
#include <math.h>
#include <stdint.h>

#define B_  2
#define H_  8
#define T_  2048
#define KD  128
#define BH  (B_*H_)
#define BN  64
#define NKT (T_/BN)      // 32 kv tiles of 64
#define NQT (T_/128)     // 16 q tiles of 128
#define NTASK (BH*NQT)   // 256
#define NELEM (BH*T_*KD)
#define GRID_MAIN 148

// ---------------- device-global scratch -----------------------------------
__device__ float d_g [BH*T_];
__device__ float d_cm[BH*T_];
__device__ float d_nf[BH*T_];
__device__ float d_ce[BH*T_];
__device__ float d_Gt[BH*NKT];
__device__ unsigned int d_task_ctr;

__device__ __nv_bfloat16 d_kh[NELEM], d_kl[NELEM];
__device__ __nv_bfloat16 d_vh[NELEM], d_vl[NELEM];

// ---------------- helpers -------------------------------------------------
__device__ __forceinline__ uint32_t smem_u32(const void* p) {
    uint32_t a;
    asm("{ .reg .u64 t; cvta.to.shared.u64 t, %1; cvt.u32.u64 %0, t; }"
        : "=r"(a) : "l"(p));
    return a;
}

#define CP16(dst, src) \
    asm volatile("cp.async.cg.shared.global [%0], [%1], 16;" :: "r"(dst), "l"(src))

#define MBAR_INIT(a, c) \
    asm volatile("mbarrier.init.shared.b64 [%0], %1;" :: "r"(a), "r"(c) : "memory")
#define MBAR_ARRIVE(a) \
    asm volatile("mbarrier.arrive.shared.b64 _, [%0];" :: "r"(a) : "memory")
#define CP_MBAR_ARRIVE(a) \
    asm volatile("cp.async.mbarrier.arrive.noinc.shared.b64 [%0];" :: "r"(a) : "memory")

__device__ __forceinline__ void mbar_wait(uint32_t a, uint32_t parity) {
    asm volatile(
        "{\n\t.reg .pred P;\n\t"
        "WL_%=:\n\t"
        "mbarrier.try_wait.parity.shared.b64 P, [%0], %1;\n\t"
        "@P bra.uni WD_%=;\n\t"
        "bra.uni WL_%=;\n\t"
        "WD_%=:\n\t}"
        :: "r"(a), "r"(parity) : "memory");
}

__device__ __forceinline__ void ldm_x4(uint32_t* r, uint32_t addr) {
    asm volatile("ldmatrix.sync.aligned.m8n8.x4.shared.b16 {%0,%1,%2,%3}, [%4];"
        : "=r"(r[0]), "=r"(r[1]), "=r"(r[2]), "=r"(r[3]) : "r"(addr));
}
__device__ __forceinline__ void ldm_x4_t(uint32_t* r, uint32_t addr) {
    asm volatile("ldmatrix.sync.aligned.m8n8.x4.trans.shared.b16 {%0,%1,%2,%3}, [%4];"
        : "=r"(r[0]), "=r"(r[1]), "=r"(r[2]), "=r"(r[3]) : "r"(addr));
}
__device__ __forceinline__ void mma16816(float (&d)[4], const uint32_t (&a)[4],
                                         uint32_t b0, uint32_t b1) {
    asm volatile(
        "mma.sync.aligned.m16n8k16.row.col.f32.bf16.bf16.f32 "
        "{%0,%1,%2,%3}, {%4,%5,%6,%7}, {%8,%9}, {%0,%1,%2,%3};"
        : "+f"(d[0]), "+f"(d[1]), "+f"(d[2]), "+f"(d[3])
        : "r"(a[0]), "r"(a[1]), "r"(a[2]), "r"(a[3]), "r"(b0), "r"(b1));
}

// fast split: hi = truncate-to-bf16, lo = RN(x - hi)
__device__ __forceinline__ void split2f(float a, float b, uint32_t& h, uint32_t& l) {
    uint32_t ua = __float_as_uint(a) & 0xffff0000u;
    uint32_t ub = __float_as_uint(b) & 0xffff0000u;
    float la = a - __uint_as_float(ua);
    float lb = b - __uint_as_float(ub);
    h = (ua >> 16) | ub;
    __nv_bfloat162 p = __float22bfloat162_rn(make_float2(la, lb));
    l = *reinterpret_cast<uint32_t*>(&p);
}

// swizzled chunk offset: 16 chunks (16B) per 256B row
__device__ __forceinline__ uint32_t swzo(int row, int ck) {
    return (uint32_t)((row * 16 + (ck ^ (row & 7))) << 4);
}

// ---------------- smem layout (bytes) -------------------------------------
#define STG_SZ 66560
#define STG(s) ((s) * STG_SZ)
#define P_KH 0
#define P_KL 16384
#define P_VH 32768
#define P_VL 49152
#define A_CE 65536
#define A_G  65792
#define MB_OFF (3 * STG_SZ)              // 199680
#define MB_EMPTY(s) (MB_OFF + (s) * 16)
#define MB_FULL(s)  (MB_OFF + (s) * 16 + 8)
#define SMEM_TOTAL (MB_OFF + 128)

// ---------------------------------------------------------------------------
// Fused pre-pass. Blocks [0,16): per-head gate scan (FIRST, overlaps splat).
// Blocks [16,4112): split K/V into bf16 hi/lo planes.
// ---------------------------------------------------------------------------
__global__ void fused_pre(const float* __restrict__ k, const float* __restrict__ v,
                          const float* __restrict__ ig, const float* __restrict__ fg) {
    __shared__ double sh[256];
    __shared__ float shf[256];
    __shared__ float tm[32];
    const int tid = threadIdx.x;

    if (blockIdx.x >= 16) {
        int i = (blockIdx.x - 16) * 256 + tid;
        float4 kv = ((const float4*)k)[i];
        float4 vv = ((const float4*)v)[i];
        uint32_t h0, l0, h1, l1;
        split2f(kv.x, kv.y, h0, l0); split2f(kv.z, kv.w, h1, l1);
        ((uint2*)d_kh)[i] = make_uint2(h0, h1);
        ((uint2*)d_kl)[i] = make_uint2(l0, l1);
        split2f(vv.x, vv.y, h0, l0); split2f(vv.z, vv.w, h1, l1);
        ((uint2*)d_vh)[i] = make_uint2(h0, h1);
        ((uint2*)d_vl)[i] = make_uint2(l0, l1);
        return;
    }

    const int bh = blockIdx.x;
    if (bh == 0 && tid == 0) d_task_ctr = GRID_MAIN;
    const float* fp = fg + (size_t)bh * T_;
    const float* ip = ig + (size_t)bh * T_;
    const int base = tid * 8;

    double lf[8]; float gi[8];
#pragma unroll
    for (int r = 0; r < 8; r++) {
        float x = fp[base + r];
        lf[r] = (double)(fminf(x, 0.f) - log1pf(__expf(-fabsf(x))));
        gi[r] = ip[base + r];
    }
    double run = 0.0, fc[8];
#pragma unroll
    for (int r = 0; r < 8; r++) { run += lf[r]; fc[r] = run; }

    sh[tid] = run; __syncthreads();
    for (int off = 1; off < 256; off <<= 1) {
        double t = 0.0; if (tid >= off) t = sh[tid - off];
        __syncthreads();
        if (tid >= off) sh[tid] += t;
        __syncthreads();
    }
    double addoff = sh[tid] - run;

    double g[8], gm[8], runm = -1e300;
#pragma unroll
    for (int r = 0; r < 8; r++) {
        fc[r] += addoff;
        g[r]  = (double)gi[r] - fc[r];
        runm  = fmax(runm, g[r]);
        gm[r] = runm;
    }
    __syncthreads();
    sh[tid] = runm; __syncthreads();
    for (int off = 1; off < 256; off <<= 1) {
        double t = -1e300; if (tid >= off) t = sh[tid - off];
        __syncthreads();
        if (tid >= off) sh[tid] = fmax(sh[tid], t);
        __syncthreads();
    }
    double prevmax = (tid == 0) ? -1e300 : sh[tid - 1];

    float gf[8];
#pragma unroll
    for (int r = 0; r < 8; r++) {
        double cm = fmax(prevmax, gm[r]);
        gf[r] = (float)g[r];
        d_g [bh*T_ + base + r] = gf[r];
        d_cm[bh*T_ + base + r] = (float)cm;
        d_nf[bh*T_ + base + r] = __expf((float)(-(fc[r] + cm)));
    }

    float lmax = gf[0];
#pragma unroll
    for (int r = 1; r < 8; r++) lmax = fmaxf(lmax, gf[r]);
    __syncthreads();
    shf[tid] = lmax; __syncthreads();
    if (tid < 32) {
        float mx = shf[tid * 8];
#pragma unroll
        for (int u = 1; u < 8; u++) mx = fmaxf(mx, shf[tid * 8 + u]);
        tm[tid] = mx;
        d_Gt[bh*NKT + tid] = mx;
    }
    __syncthreads();
    float G = tm[tid >> 3];
#pragma unroll
    for (int r = 0; r < 8; r++)
        d_ce[bh*T_ + base + r] = __expf(gf[r] - G);
}

// ---------------------------------------------------------------------------
// stage loader: K/V bf16 planes + aux into pipeline stage s (cp.async)
// ---------------------------------------------------------------------------
__device__ __forceinline__ void load_stage(uint32_t sb, int s, int bh, int kt, int tid) {
    size_t gbase = ((size_t)(bh * T_ + kt * BN)) * KD;
    const char* gkh = (const char*)d_kh + gbase * 2;
    const char* gkl = (const char*)d_kl + gbase * 2;
    const char* gvh = (const char*)d_vh + gbase * 2;
    const char* gvl = (const char*)d_vl + gbase * 2;
    uint32_t tb = sb + STG(s);
#pragma unroll
    for (int u = 0; u < 4; u++) {
        int ch = tid + u * 256;
        int r = ch >> 4, c = ch & 15;
        uint32_t a = swzo(r, c);
        size_t go = (size_t)ch * 16;
        CP16(tb + P_KH + a, gkh + go);
        CP16(tb + P_KL + a, gkl + go);
        CP16(tb + P_VH + a, gvh + go);
        CP16(tb + P_VL + a, gvl + go);
    }
    if (tid < 16) {
        CP16(tb + A_CE + tid * 16,
             (const char*)(d_ce + bh * T_ + kt * BN) + tid * 16);
    } else if (tid < 32) {
        CP16(tb + A_G + (tid - 16) * 16,
             (const char*)(d_g + bh * T_ + kt * BN) + (tid - 16) * 16);
    }
}

// ---------------------------------------------------------------------------
// Main kernel: 256 threads (8 warps), BM=128, BN=64, persistent queue,
// mbarrier 3-stage pipeline (no per-iter __syncthreads), reg-resident Q,
// chain-major MMA1, and epilogue FUSED per-kf into MMA2 (low P-reg pressure
// lets ptxas interleave next-kf ALU under current-kf MMA issue).
// ---------------------------------------------------------------------------
__global__ void __launch_bounds__(256, 1)
mlstm_mma(const float* __restrict__ q, float* __restrict__ out) {
    extern __shared__ char smem[];
    __shared__ int sh_task;
    const uint32_t sb = smem_u32(smem);
    const int tid  = threadIdx.x;
    const int lane = tid & 31;
    const int wid  = tid >> 5;
    const int m0   = wid * 16;
    const float scale = 0.08838834764831845f; // 128^-0.5

    if (tid == 0) {
#pragma unroll
        for (int s = 0; s < 3; s++) {
            MBAR_INIT(sb + MB_EMPTY(s), 256);
            MBAR_INIT(sb + MB_FULL(s), 256);
        }
    }
    __syncthreads();

    int pst = 0, pph = 1;   // producer cursor
    int cst = 0, cph = 0;   // consumer cursor

    int task = blockIdx.x;
    for (;;) {
        if (task >= NTASK) return;
        const int bh = task & 15;
        const int qt = (NQT - 1) - (task >> 4);    // descending work
        const int NT = 2 * qt + 2;
        const int q0 = qt * 128;

        // ---- stage Q planes through stage pst's tile area (transient) ----
        __syncthreads();
        {
            const float* qbase = q + (size_t)(bh * T_ + q0) * KD;
#pragma unroll
            for (int u = 0; u < 8; u++) {
                int ch = tid + u * 256;
                int r = ch >> 4, c = ch & 15;
                const float4* src = (const float4*)(qbase + r * 128 + c * 8);
                float4 x0 = src[0], x1 = src[1];
                uint32_t h0, l0, h1, l1, h2, l2, h3, l3;
                split2f(x0.x * scale, x0.y * scale, h0, l0);
                split2f(x0.z * scale, x0.w * scale, h1, l1);
                split2f(x1.x * scale, x1.y * scale, h2, l2);
                split2f(x1.z * scale, x1.w * scale, h3, l3);
                uint32_t a = swzo(r, c);
                *(uint4*)(smem + STG(pst) + 0     + a) = make_uint4(h0, h1, h2, h3);
                *(uint4*)(smem + STG(pst) + 32768 + a) = make_uint4(l0, l1, l2, l3);
            }
            __syncthreads();
        }
        uint32_t qh[8][4], ql[8][4];
#pragma unroll
        for (int kb = 0; kb < 8; kb++) {
            int row = m0 + (lane & 15);
            int ck  = 2 * kb + (lane >> 4);
            ldm_x4(qh[kb], sb + STG(pst) + 0     + swzo(row, ck));
            ldm_x4(ql[kb], sb + STG(pst) + 32768 + swzo(row, ck));
        }
        __syncthreads();

        // ---- producer: issue tile 0 ----
        mbar_wait(sb + MB_EMPTY(pst), (uint32_t)pph);
        load_stage(sb, pst, bh, 0, tid);
        CP_MBAR_ARRIVE(sb + MB_FULL(pst));
        if (++pst == 3) { pst = 0; pph ^= 1; }

        const int rowg0 = q0 + m0 + (lane >> 2);
        const int rowg1 = rowg0 + 8;
        const float cm0 = d_cm[bh * T_ + rowg0];
        const float cm1 = d_cm[bh * T_ + rowg1];
        const float nf0 = d_nf[bh * T_ + rowg0];
        const float nf1 = d_nf[bh * T_ + rowg1];

        float hacc[16][4];
#pragma unroll
        for (int i = 0; i < 16; i++)
#pragma unroll
            for (int j = 0; j < 4; j++) hacc[i][j] = 0.f;
        float rs0 = 0.f, rs1 = 0.f;

        for (int kt = 0; kt < NT; kt++) {
            // ---- producer: prefetch tile kt+1 ----
            if (kt + 1 < NT) {
                mbar_wait(sb + MB_EMPTY(pst), (uint32_t)pph);
                load_stage(sb, pst, bh, kt + 1, tid);
                CP_MBAR_ARRIVE(sb + MB_FULL(pst));
                if (++pst == 3) { pst = 0; pph ^= 1; }
            }

            // ---- consumer: wait tile kt ----
            mbar_wait(sb + MB_FULL(cst), (uint32_t)cph);
            const uint32_t tb = sb + STG(cst);
            const float Gtv = __ldg(&d_Gt[bh * NKT + kt]);

            const int  smin = kt * BN;
            const int  wmrow = q0 + m0;
            const bool fullmask = (smin > wmrow + 15);
            const bool partial  = !fullmask && (smin + BN - 1 > wmrow);

            if (!fullmask) {
                // ================= MMA1: S = Qs.K^T (chain-major) ===========
                float sa[8][4];
#pragma unroll
                for (int i = 0; i < 8; i++)
#pragma unroll
                    for (int j = 0; j < 4; j++) sa[i][j] = 0.f;

#pragma unroll
                for (int kb = 0; kb < 8; kb++) {
                    const int brow = (lane & 7) + ((lane >> 4) << 3);
                    const int bck  = 2 * kb + ((lane >> 3) & 1);
                    uint32_t bhf[4][4];
#pragma unroll
                    for (int np = 0; np < 4; np++)
                        ldm_x4(bhf[np], tb + P_KH + swzo(16 * np + brow, bck));
#pragma unroll
                    for (int np = 0; np < 4; np++) {
                        mma16816(sa[2*np],   qh[kb], bhf[np][0], bhf[np][1]);
                        mma16816(sa[2*np+1], qh[kb], bhf[np][2], bhf[np][3]);
                    }
                    uint32_t blf[4][4];
#pragma unroll
                    for (int np = 0; np < 4; np++)
                        ldm_x4(blf[np], tb + P_KL + swzo(16 * np + brow, bck));
#pragma unroll
                    for (int np = 0; np < 4; np++) {
                        mma16816(sa[2*np],   ql[kb], bhf[np][0], bhf[np][1]);
                        mma16816(sa[2*np+1], ql[kb], bhf[np][2], bhf[np][3]);
                    }
#pragma unroll
                    for (int np = 0; np < 4; np++) {
                        mma16816(sa[2*np],   qh[kb], blf[np][0], blf[np][1]);
                        mma16816(sa[2*np+1], qh[kb], blf[np][2], blf[np][3]);
                    }
                }

                // ============ fused epilogue + MMA2, per kf =================
                const float* ce = (const float*)(smem + STG(cst) + A_CE);
                const float* gg = (const float*)(smem + STG(cst) + A_G);
                const float rr0 = __expf(Gtv - cm0);
                const float rr1 = __expf(Gtv - cm1);
#pragma unroll
                for (int kf = 0; kf < 4; kf++) {
                    // --- epilogue for nb = 2kf, 2kf+1 -> P fragments ---
                    uint32_t phf4[4], plf4[4];
#pragma unroll
                    for (int half = 0; half < 2; half++) {
                        const int nb = 2 * kf + half;
                        int n0 = 8 * nb + 2 * (lane & 3);
                        float p0, p1, p2, p3;
                        if (!partial) {
                            float c0 = ce[n0], c1 = ce[n0 + 1];
                            p0 = sa[nb][0] * rr0 * c0; p1 = sa[nb][1] * rr0 * c1;
                            p2 = sa[nb][2] * rr1 * c0; p3 = sa[nb][3] * rr1 * c1;
                        } else {
                            int s0g = smin + n0;
                            float g0 = gg[n0], g1 = gg[n0 + 1];
                            p0 = (s0g     <= rowg0) ? sa[nb][0] * __expf(g0 - cm0) : 0.f;
                            p1 = (s0g + 1 <= rowg0) ? sa[nb][1] * __expf(g1 - cm0) : 0.f;
                            p2 = (s0g     <= rowg1) ? sa[nb][2] * __expf(g0 - cm1) : 0.f;
                            p3 = (s0g + 1 <= rowg1) ? sa[nb][3] * __expf(g1 - cm1) : 0.f;
                        }
                        rs0 += p0 + p1; rs1 += p2 + p3;
                        split2f(p0, p1, phf4[2*half],     plf4[2*half]);
                        split2f(p2, p3, phf4[2*half + 1], plf4[2*half + 1]);
                    }

                    // --- MMA2 for this kf ---
                    const int vrow = 16 * kf + (lane & 7) + (((lane >> 3) & 1) << 3);
#pragma unroll
                    for (int grp = 0; grp < 2; grp++) {
                        uint32_t vhf[4][4];
#pragma unroll
                        for (int j = 0; j < 4; j++) {
                            int ck = 2 * (grp * 4 + j) + (lane >> 4);
                            ldm_x4_t(vhf[j], tb + P_VH + swzo(vrow, ck));
                        }
#pragma unroll
                        for (int j = 0; j < 4; j++) {
                            int t = 8 * grp + 2 * j;
                            mma16816(hacc[t],   phf4, vhf[j][0], vhf[j][1]);
                            mma16816(hacc[t+1], phf4, vhf[j][2], vhf[j][3]);
                        }
                        uint32_t vlf[4][4];
#pragma unroll
                        for (int j = 0; j < 4; j++) {
                            int ck = 2 * (grp * 4 + j) + (lane >> 4);
                            ldm_x4_t(vlf[j], tb + P_VL + swzo(vrow, ck));
                        }
#pragma unroll
                        for (int j = 0; j < 4; j++) {
                            int t = 8 * grp + 2 * j;
                            mma16816(hacc[t],   phf4, vlf[j][0], vlf[j][1]);
                            mma16816(hacc[t+1], phf4, vlf[j][2], vlf[j][3]);
                        }
#pragma unroll
                        for (int j = 0; j < 4; j++) {
                            int t = 8 * grp + 2 * j;
                            mma16816(hacc[t],   plf4, vhf[j][0], vhf[j][1]);
                            mma16816(hacc[t+1], plf4, vhf[j][2], vhf[j][3]);
                        }
                    }
                }
            }

            // ---- consumer: release tile kt ----
            MBAR_ARRIVE(sb + MB_EMPTY(cst));
            if (++cst == 3) { cst = 0; cph ^= 1; }
        }

        // ---- reduce rowsums, normalize, write ----
        rs0 += __shfl_xor_sync(0xffffffffu, rs0, 1);
        rs0 += __shfl_xor_sync(0xffffffffu, rs0, 2);
        rs1 += __shfl_xor_sync(0xffffffffu, rs1, 1);
        rs1 += __shfl_xor_sync(0xffffffffu, rs1, 2);
        const float inv0 = 1.f / fmaxf(fabsf(rs0), nf0);
        const float inv1 = 1.f / fmaxf(fabsf(rs1), nf1);
        float* o0 = out + ((size_t)(bh * T_ + rowg0)) * KD;
        float* o1 = out + ((size_t)(bh * T_ + rowg1)) * KD;
#pragma unroll
        for (int nb = 0; nb < 16; nb++) {
            int c = 8 * nb + 2 * (lane & 3);
            *(float2*)(o0 + c) = make_float2(hacc[nb][0] * inv0, hacc[nb][1] * inv0);
            *(float2*)(o1 + c) = make_float2(hacc[nb][2] * inv1, hacc[nb][3] * inv1);
        }

        // ---- next task ----
        if (tid == 0) sh_task = (int)atomicAdd(&d_task_ctr, 1u);
        __syncthreads();
        task = sh_task;
    }
}

// ---------------------------------------------------------------------------
extern "C" void kernel_launch(void* const* d_in, const int* in_sizes, int n_in,
                              void* d_out, int out_size) {
    const float* q  = (const float*)d_in[0];
    const float* k  = (const float*)d_in[1];
    const float* v  = (const float*)d_in[2];
    const float* ig = (const float*)d_in[3];
    const float* fg = (const float*)d_in[4];
    float* out = (float*)d_out;

    fused_pre<<<4096 + 16, 256>>>(k, v, ig, fg);

    cudaFuncSetAttribute(mlstm_mma,
                         cudaFuncAttributeMaxDynamicSharedMemorySize, SMEM_TOTAL);
    mlstm_mma<<<GRID_MAIN, 256, SMEM_TOTAL>>>(q, out);
}

// round 17
// speedup vs baseline: 1.1525x; 1.0102x over previous
#include <cuda_runtime.h>
#include <cuda_bf16.h>
#include <math.h>
#include <stdint.h>

#define B_  2
#define H_  8
#define T_  2048
#define KD  128
#define BH  (B_*H_)
#define BN  64
#define NKT (T_/BN)      // 32 kv tiles of 64
#define NQT (T_/128)     // 16 q tiles of 128
#define NTASK (BH*NQT)   // 256
#define NELEM (BH*T_*KD)
#define GRID_MAIN 148

// ---------------- device-global scratch -----------------------------------
__device__ float d_g [BH*T_];
__device__ float d_cm[BH*T_];
__device__ float d_nf[BH*T_];
__device__ float d_ce[BH*T_];
__device__ float d_Gt[BH*NKT];
__device__ unsigned int d_task_ctr;

__device__ __nv_bfloat16 d_kh[NELEM], d_kl[NELEM];
__device__ __nv_bfloat16 d_vh[NELEM], d_vl[NELEM];

// ---------------- helpers -------------------------------------------------
__device__ __forceinline__ uint32_t smem_u32(const void* p) {
    uint32_t a;
    asm("{ .reg .u64 t; cvta.to.shared.u64 t, %1; cvt.u32.u64 %0, t; }"
        : "=r"(a) : "l"(p));
    return a;
}

#define CP16(dst, src) \
    asm volatile("cp.async.cg.shared.global [%0], [%1], 16;" :: "r"(dst), "l"(src))

#define MBAR_INIT(a, c) \
    asm volatile("mbarrier.init.shared.b64 [%0], %1;" :: "r"(a), "r"(c) : "memory")
#define MBAR_ARRIVE(a) \
    asm volatile("mbarrier.arrive.shared.b64 _, [%0];" :: "r"(a) : "memory")
#define CP_MBAR_ARRIVE(a) \
    asm volatile("cp.async.mbarrier.arrive.noinc.shared.b64 [%0];" :: "r"(a) : "memory")

__device__ __forceinline__ void mbar_wait(uint32_t a, uint32_t parity) {
    asm volatile(
        "{\n\t.reg .pred P;\n\t"
        "WL_%=:\n\t"
        "mbarrier.try_wait.parity.shared.b64 P, [%0], %1;\n\t"
        "@P bra.uni WD_%=;\n\t"
        "bra.uni WL_%=;\n\t"
        "WD_%=:\n\t}"
        :: "r"(a), "r"(parity) : "memory");
}

__device__ __forceinline__ void ldm_x4(uint32_t* r, uint32_t addr) {
    asm volatile("ldmatrix.sync.aligned.m8n8.x4.shared.b16 {%0,%1,%2,%3}, [%4];"
        : "=r"(r[0]), "=r"(r[1]), "=r"(r[2]), "=r"(r[3]) : "r"(addr));
}
__device__ __forceinline__ void ldm_x4_t(uint32_t* r, uint32_t addr) {
    asm volatile("ldmatrix.sync.aligned.m8n8.x4.trans.shared.b16 {%0,%1,%2,%3}, [%4];"
        : "=r"(r[0]), "=r"(r[1]), "=r"(r[2]), "=r"(r[3]) : "r"(addr));
}
__device__ __forceinline__ void mma16816(float (&d)[4], const uint32_t (&a)[4],
                                         uint32_t b0, uint32_t b1) {
    asm volatile(
        "mma.sync.aligned.m16n8k16.row.col.f32.bf16.bf16.f32 "
        "{%0,%1,%2,%3}, {%4,%5,%6,%7}, {%8,%9}, {%0,%1,%2,%3};"
        : "+f"(d[0]), "+f"(d[1]), "+f"(d[2]), "+f"(d[3])
        : "r"(a[0]), "r"(a[1]), "r"(a[2]), "r"(a[3]), "r"(b0), "r"(b1));
}

// fast split: hi = truncate-to-bf16, lo = RN(x - hi)
__device__ __forceinline__ void split2f(float a, float b, uint32_t& h, uint32_t& l) {
    uint32_t ua = __float_as_uint(a) & 0xffff0000u;
    uint32_t ub = __float_as_uint(b) & 0xffff0000u;
    float la = a - __uint_as_float(ua);
    float lb = b - __uint_as_float(ub);
    h = (ua >> 16) | ub;
    __nv_bfloat162 p = __float22bfloat162_rn(make_float2(la, lb));
    l = *reinterpret_cast<uint32_t*>(&p);
}

// swizzled chunk offset: 16 chunks (16B) per 256B row
__device__ __forceinline__ uint32_t swzo(int row, int ck) {
    return (uint32_t)((row * 16 + (ck ^ (row & 7))) << 4);
}

// ---------------- smem layout (bytes) -------------------------------------
// 3 tile stages (64KB each, 1024-aligned), persistent Q-lo plane (32KB),
// per-stage aux vectors in a separate region, mbarriers at the end.
#define STG_SZ 65536
#define STG(s) ((s) * STG_SZ)
#define P_KH 0
#define P_KL 16384
#define P_VH 32768
#define P_VL 49152
#define QLO_OFF 196608                    // 32KB persistent Q-lo plane
#define AUX_OFF 229376
#define A_CE(s) (AUX_OFF + (s) * 512)
#define A_G(s)  (AUX_OFF + (s) * 512 + 256)
#define MB_OFF  (AUX_OFF + 1536)          // 230912
#define MB_EMPTY(s) (MB_OFF + (s) * 16)
#define MB_FULL(s)  (MB_OFF + (s) * 16 + 8)
#define SMEM_TOTAL (MB_OFF + 128)         // 231040 <= 232448 (227KB)

// ---------------------------------------------------------------------------
// Fused pre-pass. Blocks [0,16): per-head gate scan (FIRST, overlaps splat).
// Blocks [16,4112): split K/V into bf16 hi/lo planes.
// ---------------------------------------------------------------------------
__global__ void fused_pre(const float* __restrict__ k, const float* __restrict__ v,
                          const float* __restrict__ ig, const float* __restrict__ fg) {
    __shared__ double sh[256];
    __shared__ float shf[256];
    __shared__ float tm[32];
    const int tid = threadIdx.x;

    if (blockIdx.x >= 16) {
        int i = (blockIdx.x - 16) * 256 + tid;
        float4 kv = ((const float4*)k)[i];
        float4 vv = ((const float4*)v)[i];
        uint32_t h0, l0, h1, l1;
        split2f(kv.x, kv.y, h0, l0); split2f(kv.z, kv.w, h1, l1);
        ((uint2*)d_kh)[i] = make_uint2(h0, h1);
        ((uint2*)d_kl)[i] = make_uint2(l0, l1);
        split2f(vv.x, vv.y, h0, l0); split2f(vv.z, vv.w, h1, l1);
        ((uint2*)d_vh)[i] = make_uint2(h0, h1);
        ((uint2*)d_vl)[i] = make_uint2(l0, l1);
        return;
    }

    const int bh = blockIdx.x;
    if (bh == 0 && tid == 0) d_task_ctr = GRID_MAIN;
    const float* fp = fg + (size_t)bh * T_;
    const float* ip = ig + (size_t)bh * T_;
    const int base = tid * 8;

    double lf[8]; float gi[8];
#pragma unroll
    for (int r = 0; r < 8; r++) {
        float x = fp[base + r];
        lf[r] = (double)(fminf(x, 0.f) - log1pf(__expf(-fabsf(x))));
        gi[r] = ip[base + r];
    }
    double run = 0.0, fc[8];
#pragma unroll
    for (int r = 0; r < 8; r++) { run += lf[r]; fc[r] = run; }

    sh[tid] = run; __syncthreads();
    for (int off = 1; off < 256; off <<= 1) {
        double t = 0.0; if (tid >= off) t = sh[tid - off];
        __syncthreads();
        if (tid >= off) sh[tid] += t;
        __syncthreads();
    }
    double addoff = sh[tid] - run;

    double g[8], gm[8], runm = -1e300;
#pragma unroll
    for (int r = 0; r < 8; r++) {
        fc[r] += addoff;
        g[r]  = (double)gi[r] - fc[r];
        runm  = fmax(runm, g[r]);
        gm[r] = runm;
    }
    __syncthreads();
    sh[tid] = runm; __syncthreads();
    for (int off = 1; off < 256; off <<= 1) {
        double t = -1e300; if (tid >= off) t = sh[tid - off];
        __syncthreads();
        if (tid >= off) sh[tid] = fmax(sh[tid], t);
        __syncthreads();
    }
    double prevmax = (tid == 0) ? -1e300 : sh[tid - 1];

    float gf[8];
#pragma unroll
    for (int r = 0; r < 8; r++) {
        double cm = fmax(prevmax, gm[r]);
        gf[r] = (float)g[r];
        d_g [bh*T_ + base + r] = gf[r];
        d_cm[bh*T_ + base + r] = (float)cm;
        d_nf[bh*T_ + base + r] = __expf((float)(-(fc[r] + cm)));
    }

    float lmax = gf[0];
#pragma unroll
    for (int r = 1; r < 8; r++) lmax = fmaxf(lmax, gf[r]);
    __syncthreads();
    shf[tid] = lmax; __syncthreads();
    if (tid < 32) {
        float mx = shf[tid * 8];
#pragma unroll
        for (int u = 1; u < 8; u++) mx = fmaxf(mx, shf[tid * 8 + u]);
        tm[tid] = mx;
        d_Gt[bh*NKT + tid] = mx;
    }
    __syncthreads();
    float G = tm[tid >> 3];
#pragma unroll
    for (int r = 0; r < 8; r++)
        d_ce[bh*T_ + base + r] = __expf(gf[r] - G);
}

// ---------------------------------------------------------------------------
// stage loader: K/V bf16 planes into stage s + aux into aux region (cp.async)
// ---------------------------------------------------------------------------
__device__ __forceinline__ void load_stage(uint32_t sb, int s, int bh, int kt, int tid) {
    size_t gbase = ((size_t)(bh * T_ + kt * BN)) * KD;
    const char* gkh = (const char*)d_kh + gbase * 2;
    const char* gkl = (const char*)d_kl + gbase * 2;
    const char* gvh = (const char*)d_vh + gbase * 2;
    const char* gvl = (const char*)d_vl + gbase * 2;
    uint32_t tb = sb + STG(s);
#pragma unroll
    for (int u = 0; u < 4; u++) {
        int ch = tid + u * 256;
        int r = ch >> 4, c = ch & 15;
        uint32_t a = swzo(r, c);
        size_t go = (size_t)ch * 16;
        CP16(tb + P_KH + a, gkh + go);
        CP16(tb + P_KL + a, gkl + go);
        CP16(tb + P_VH + a, gvh + go);
        CP16(tb + P_VL + a, gvl + go);
    }
    if (tid < 16) {
        CP16(sb + A_CE(s) + tid * 16,
             (const char*)(d_ce + bh * T_ + kt * BN) + tid * 16);
    } else if (tid < 32) {
        CP16(sb + A_G(s) + (tid - 16) * 16,
             (const char*)(d_g + bh * T_ + kt * BN) + (tid - 16) * 16);
    }
}

// ---------------------------------------------------------------------------
// Main kernel: 256 threads (8 warps), BM=128, BN=64, persistent queue,
// mbarrier 3-stage pipeline, chain-major MMA. First-plane B/V fragments
// (bhf/vhf) register-double-buffered one step ahead (full chain-group
// shadow); Q-lo fragments reloaded per-kb from a persistent 32KB smem plane.
// ---------------------------------------------------------------------------
__global__ void __launch_bounds__(256, 1)
mlstm_mma(const float* __restrict__ q, float* __restrict__ out) {
    extern __shared__ char smem[];
    __shared__ int sh_task;
    const uint32_t sb = smem_u32(smem);
    const int tid  = threadIdx.x;
    const int lane = tid & 31;
    const int wid  = tid >> 5;
    const int m0   = wid * 16;
    const float scale = 0.08838834764831845f; // 128^-0.5

    if (tid == 0) {
#pragma unroll
        for (int s = 0; s < 3; s++) {
            MBAR_INIT(sb + MB_EMPTY(s), 256);
            MBAR_INIT(sb + MB_FULL(s), 256);
        }
    }
    __syncthreads();

    int pst = 0, pph = 1;   // producer cursor
    int cst = 0, cph = 0;   // consumer cursor

    int task = blockIdx.x;
    for (;;) {
        if (task >= NTASK) return;
        const int bh = task & 15;
        const int qt = (NQT - 1) - (task >> 4);    // descending work
        const int NT = 2 * qt + 2;
        const int q0 = qt * 128;

        // ---- stage Q: hi -> stage pst (transient), lo -> QLO (persistent) --
        __syncthreads();
        {
            const float* qbase = q + (size_t)(bh * T_ + q0) * KD;
#pragma unroll
            for (int u = 0; u < 8; u++) {
                int ch = tid + u * 256;
                int r = ch >> 4, c = ch & 15;
                const float4* src = (const float4*)(qbase + r * 128 + c * 8);
                float4 x0 = src[0], x1 = src[1];
                uint32_t h0, l0, h1, l1, h2, l2, h3, l3;
                split2f(x0.x * scale, x0.y * scale, h0, l0);
                split2f(x0.z * scale, x0.w * scale, h1, l1);
                split2f(x1.x * scale, x1.y * scale, h2, l2);
                split2f(x1.z * scale, x1.w * scale, h3, l3);
                uint32_t a = swzo(r, c);
                *(uint4*)(smem + STG(pst) + a) = make_uint4(h0, h1, h2, h3);
                *(uint4*)(smem + QLO_OFF  + a) = make_uint4(l0, l1, l2, l3);
            }
            __syncthreads();
        }
        uint32_t qh[8][4];
#pragma unroll
        for (int kb = 0; kb < 8; kb++) {
            int row = m0 + (lane & 15);
            int ck  = 2 * kb + (lane >> 4);
            ldm_x4(qh[kb], sb + STG(pst) + swzo(row, ck));
        }
        __syncthreads();

        // ---- producer: issue tile 0 ----
        mbar_wait(sb + MB_EMPTY(pst), (uint32_t)pph);
        load_stage(sb, pst, bh, 0, tid);
        CP_MBAR_ARRIVE(sb + MB_FULL(pst));
        if (++pst == 3) { pst = 0; pph ^= 1; }

        const int rowg0 = q0 + m0 + (lane >> 2);
        const int rowg1 = rowg0 + 8;
        const float cm0 = d_cm[bh * T_ + rowg0];
        const float cm1 = d_cm[bh * T_ + rowg1];
        const float nf0 = d_nf[bh * T_ + rowg0];
        const float nf1 = d_nf[bh * T_ + rowg1];

        float hacc[16][4];
#pragma unroll
        for (int i = 0; i < 16; i++)
#pragma unroll
            for (int j = 0; j < 4; j++) hacc[i][j] = 0.f;
        float rs0 = 0.f, rs1 = 0.f;

        for (int kt = 0; kt < NT; kt++) {
            // ---- producer: prefetch tile kt+1 ----
            if (kt + 1 < NT) {
                mbar_wait(sb + MB_EMPTY(pst), (uint32_t)pph);
                load_stage(sb, pst, bh, kt + 1, tid);
                CP_MBAR_ARRIVE(sb + MB_FULL(pst));
                if (++pst == 3) { pst = 0; pph ^= 1; }
            }

            // ---- consumer: wait tile kt ----
            mbar_wait(sb + MB_FULL(cst), (uint32_t)cph);
            const uint32_t tb = sb + STG(cst);
            const float Gtv = __ldg(&d_Gt[bh * NKT + kt]);

            const int  smin = kt * BN;
            const int  wmrow = q0 + m0;
            const bool fullmask = (smin > wmrow + 15);
            const bool partial  = !fullmask && (smin + BN - 1 > wmrow);

            if (!fullmask) {
                const int brow = (lane & 7) + ((lane >> 4) << 3);
                const int bsel = (lane >> 3) & 1;

                // ================= MMA1: S = Qs.K^T =========================
                float sa[8][4];
#pragma unroll
                for (int i = 0; i < 8; i++)
#pragma unroll
                    for (int j = 0; j < 4; j++) sa[i][j] = 0.f;

                uint32_t bhf[2][4][4];
#pragma unroll
                for (int np = 0; np < 4; np++)     // preload kb=0 K-hi
                    ldm_x4(bhf[0][np], tb + P_KH + swzo(16 * np + brow, bsel));

#pragma unroll
                for (int kb = 0; kb < 8; kb++) {
                    const int cur = kb & 1, nxt = cur ^ 1;
                    // Q-lo fragment for this kb (consumed by chain 2)
                    uint32_t qlf[4];
                    ldm_x4(qlf, sb + QLO_OFF + swzo(m0 + (lane & 15),
                                                    2 * kb + (lane >> 4)));
                    // K-lo fragments (consumed by chain 3)
                    uint32_t blf[4][4];
#pragma unroll
                    for (int np = 0; np < 4; np++)
                        ldm_x4(blf[np], tb + P_KL + swzo(16 * np + brow,
                                                         2 * kb + bsel));
                    // prefetch next kb's K-hi (consumed next iteration)
                    if (kb < 7) {
#pragma unroll
                        for (int np = 0; np < 4; np++)
                            ldm_x4(bhf[nxt][np], tb + P_KH +
                                   swzo(16 * np + brow, 2 * (kb + 1) + bsel));
                    }
                    // chain 1: qh x kh (operands resident since last kb)
#pragma unroll
                    for (int np = 0; np < 4; np++) {
                        mma16816(sa[2*np],   qh[kb], bhf[cur][np][0], bhf[cur][np][1]);
                        mma16816(sa[2*np+1], qh[kb], bhf[cur][np][2], bhf[cur][np][3]);
                    }
                    // chain 2: ql x kh (qlf shadowed by chain 1)
#pragma unroll
                    for (int np = 0; np < 4; np++) {
                        mma16816(sa[2*np],   qlf, bhf[cur][np][0], bhf[cur][np][1]);
                        mma16816(sa[2*np+1], qlf, bhf[cur][np][2], bhf[cur][np][3]);
                    }
                    // chain 3: qh x kl (blf shadowed by chains 1-2)
#pragma unroll
                    for (int np = 0; np < 4; np++) {
                        mma16816(sa[2*np],   qh[kb], blf[np][0], blf[np][1]);
                        mma16816(sa[2*np+1], qh[kb], blf[np][2], blf[np][3]);
                    }
                }

                // ============ fused epilogue + MMA2, per kf =================
                const float* ce = (const float*)(smem + A_CE(cst));
                const float* gg = (const float*)(smem + A_G(cst));
                const float rr0 = __expf(Gtv - cm0);
                const float rr1 = __expf(Gtv - cm1);

                uint32_t vhf[2][4][4];
                {   // preload unit 0 (kf=0, grp=0) V-hi
                    int vrow0 = (lane & 7) + (((lane >> 3) & 1) << 3);
#pragma unroll
                    for (int j = 0; j < 4; j++)
                        ldm_x4_t(vhf[0][j], tb + P_VH +
                                 swzo(vrow0, 2 * j + (lane >> 4)));
                }

#pragma unroll
                for (int kf = 0; kf < 4; kf++) {
                    // --- epilogue for nb = 2kf, 2kf+1 -> P fragments ---
                    uint32_t phf4[4], plf4[4];
#pragma unroll
                    for (int half = 0; half < 2; half++) {
                        const int nb = 2 * kf + half;
                        int n0 = 8 * nb + 2 * (lane & 3);
                        float p0, p1, p2, p3;
                        if (!partial) {
                            float c0 = ce[n0], c1 = ce[n0 + 1];
                            p0 = sa[nb][0] * rr0 * c0; p1 = sa[nb][1] * rr0 * c1;
                            p2 = sa[nb][2] * rr1 * c0; p3 = sa[nb][3] * rr1 * c1;
                        } else {
                            int s0g = smin + n0;
                            float g0 = gg[n0], g1 = gg[n0 + 1];
                            p0 = (s0g     <= rowg0) ? sa[nb][0] * __expf(g0 - cm0) : 0.f;
                            p1 = (s0g + 1 <= rowg0) ? sa[nb][1] * __expf(g1 - cm0) : 0.f;
                            p2 = (s0g     <= rowg1) ? sa[nb][2] * __expf(g0 - cm1) : 0.f;
                            p3 = (s0g + 1 <= rowg1) ? sa[nb][3] * __expf(g1 - cm1) : 0.f;
                        }
                        rs0 += p0 + p1; rs1 += p2 + p3;
                        split2f(p0, p1, phf4[2*half],     plf4[2*half]);
                        split2f(p2, p3, phf4[2*half + 1], plf4[2*half + 1]);
                    }

                    // --- MMA2 for this kf (units u = 2kf+grp) ---
                    const int vrow = 16 * kf + (lane & 7) + (((lane >> 3) & 1) << 3);
#pragma unroll
                    for (int grp = 0; grp < 2; grp++) {
                        const int u = 2 * kf + grp, cur = u & 1, nxt = cur ^ 1;
                        // V-lo for this unit (shadowed by chains 1-2 below)
                        uint32_t vlf[4][4];
#pragma unroll
                        for (int j = 0; j < 4; j++)
                            ldm_x4_t(vlf[j], tb + P_VL +
                                     swzo(vrow, 2 * (grp * 4 + j) + (lane >> 4)));
                        // prefetch next unit's V-hi
                        if (u < 7) {
                            const int kf2 = (u + 1) >> 1, grp2 = (u + 1) & 1;
                            const int vrow2 = 16 * kf2 + (lane & 7)
                                            + (((lane >> 3) & 1) << 3);
#pragma unroll
                            for (int j = 0; j < 4; j++)
                                ldm_x4_t(vhf[nxt][j], tb + P_VH +
                                         swzo(vrow2, 2 * (grp2 * 4 + j) + (lane >> 4)));
                        }
                        // chain 1: ph x vh (resident since previous unit)
#pragma unroll
                        for (int j = 0; j < 4; j++) {
                            int t = 8 * grp + 2 * j;
                            mma16816(hacc[t],   phf4, vhf[cur][j][0], vhf[cur][j][1]);
                            mma16816(hacc[t+1], phf4, vhf[cur][j][2], vhf[cur][j][3]);
                        }
                        // chain 2: pl x vh
#pragma unroll
                        for (int j = 0; j < 4; j++) {
                            int t = 8 * grp + 2 * j;
                            mma16816(hacc[t],   plf4, vhf[cur][j][0], vhf[cur][j][1]);
                            mma16816(hacc[t+1], plf4, vhf[cur][j][2], vhf[cur][j][3]);
                        }
                        // chain 3: ph x vl (vlf shadowed by chains 1-2)
#pragma unroll
                        for (int j = 0; j < 4; j++) {
                            int t = 8 * grp + 2 * j;
                            mma16816(hacc[t],   phf4, vlf[j][0], vlf[j][1]);
                            mma16816(hacc[t+1], phf4, vlf[j][2], vlf[j][3]);
                        }
                    }
                }
            }

            // ---- consumer: release tile kt ----
            MBAR_ARRIVE(sb + MB_EMPTY(cst));
            if (++cst == 3) { cst = 0; cph ^= 1; }
        }

        // ---- reduce rowsums, normalize, write ----
        rs0 += __shfl_xor_sync(0xffffffffu, rs0, 1);
        rs0 += __shfl_xor_sync(0xffffffffu, rs0, 2);
        rs1 += __shfl_xor_sync(0xffffffffu, rs1, 1);
        rs1 += __shfl_xor_sync(0xffffffffu, rs1, 2);
        const float inv0 = 1.f / fmaxf(fabsf(rs0), nf0);
        const float inv1 = 1.f / fmaxf(fabsf(rs1), nf1);
        float* o0 = out + ((size_t)(bh * T_ + rowg0)) * KD;
        float* o1 = out + ((size_t)(bh * T_ + rowg1)) * KD;
#pragma unroll
        for (int nb = 0; nb < 16; nb++) {
            int c = 8 * nb + 2 * (lane & 3);
            *(float2*)(o0 + c) = make_float2(hacc[nb][0] * inv0, hacc[nb][1] * inv0);
            *(float2*)(o1 + c) = make_float2(hacc[nb][2] * inv1, hacc[nb][3] * inv1);
        }

        // ---- next task ----
        if (tid == 0) sh_task = (int)atomicAdd(&d_task_ctr, 1u);
        __syncthreads();
        task = sh_task;
    }
}

// ---------------------------------------------------------------------------
extern "C" void kernel_launch(void* const* d_in, const int* in_sizes, int n_in,
                              void* d_out, int out_size) {
    const float* q  = (const float*)d_in[0];
    const float* k  = (const float*)d_in[1];
    const float* v  = (const float*)d_in[2];
    const float* ig = (const float*)d_in[3];
    const float* fg = (const float*)d_in[4];
    float* out = (float*)d_out;

    fused_pre<<<4096 + 16, 256>>>(k, v, ig, fg);

    cudaFuncSetAttribute(mlstm_mma,
                         cudaFuncAttributeMaxDynamicSharedMemorySize, SMEM_TOTAL);
    mlstm_mma<<<GRID_MAIN, 256, SMEM_TOTAL>>>(q, out);
}